// round 1
// baseline (speedup 1.0000x reference)
#include <cuda_runtime.h>
#include <math.h>

// ---------------------------------------------------------------------------
// Problem constants
// ---------------------------------------------------------------------------
#define BB   4
#define TT   2048
#define CC   768
#define HH   12
#define DD   64
#define MLPD 3072
#define MR   (BB*TT)        /* 8192 rows */
#define QKVN (3*CC)         /* 2304 */
#define NBH  (BB*HH)        /* 48 */

__device__ __constant__ float c_scale = 0.03608439182435161f; /* 768^-0.5 */

// ---------------------------------------------------------------------------
// Scratch (device globals; no allocation allowed)
// ---------------------------------------------------------------------------
__device__ float g_xn  [MR * CC];                 // 25 MB
__device__ float g_wqkv[CC * QKVN];               // 7 MB
__device__ float g_qkv [MR * QKVN];               // 75 MB
__device__ float g_S   [(long long)NBH * TT * TT];// 805 MB
__device__ float g_attn[MR * CC];                 // 25 MB
__device__ float g_x2  [MR * CC];                 // 25 MB
__device__ float g_y   [MR * CC];                 // 25 MB
__device__ float g_h1  [MR * MLPD];               // 100 MB

// ---------------------------------------------------------------------------
// Repack Wq/Wk/Wv [H,C,D] into a single row-major [C, 3C] matrix
// col n = s*768 + h*64 + d   (s = 0:q, 1:k, 2:v)
// ---------------------------------------------------------------------------
__global__ void repack_kernel(const float* __restrict__ Wq,
                              const float* __restrict__ Wk,
                              const float* __restrict__ Wv,
                              float* __restrict__ out) {
    int i = blockIdx.x * 256 + threadIdx.x;
    if (i >= CC * QKVN) return;
    int c  = i / QKVN;
    int n  = i % QKVN;
    int s  = n / CC;
    int hd = n % CC;
    int h  = hd / DD;
    int d  = hd % DD;
    const float* W = (s == 0) ? Wq : ((s == 1) ? Wk : Wv);
    out[i] = W[((long long)h * CC + c) * DD + d];
}

// ---------------------------------------------------------------------------
// LayerNorm: one block per row, 256 threads, C=768 (3 elems/thread)
// ---------------------------------------------------------------------------
__global__ void ln_kernel(const float* __restrict__ x,
                          const float* __restrict__ g,
                          const float* __restrict__ b,
                          float* __restrict__ out) {
    int row = blockIdx.x;
    int tid = threadIdx.x;
    const float* xr = x + (long long)row * CC;
    float*       orow = out + (long long)row * CC;

    float v0 = xr[tid], v1 = xr[tid + 256], v2 = xr[tid + 512];
    float s  = v0 + v1 + v2;
    float s2 = v0 * v0 + v1 * v1 + v2 * v2;

    __shared__ float sh1[256], sh2[256];
    sh1[tid] = s; sh2[tid] = s2;
    __syncthreads();
    #pragma unroll
    for (int o = 128; o > 0; o >>= 1) {
        if (tid < o) { sh1[tid] += sh1[tid + o]; sh2[tid] += sh2[tid + o]; }
        __syncthreads();
    }
    float mean = sh1[0] * (1.0f / CC);
    float var  = sh2[0] * (1.0f / CC) - mean * mean;
    float rstd = rsqrtf(var + 1e-6f);

    orow[tid]       = (v0 - mean) * rstd * g[tid]       + b[tid];
    orow[tid + 256] = (v1 - mean) * rstd * g[tid + 256] + b[tid + 256];
    orow[tid + 512] = (v2 - mean) * rstd * g[tid + 512] + b[tid + 512];
}

// ---------------------------------------------------------------------------
// Device GELU (exact, erf-based)
// ---------------------------------------------------------------------------
__device__ __forceinline__ float gelu_exact(float v) {
    return 0.5f * v * (1.0f + erff(v * 0.70710678118654752f));
}

// ---------------------------------------------------------------------------
// Generic tiled SGEMM: C = act(A*B + bias) + res
//   A: [M,K] lda, batched via z*strideA
//   B: [K,N] ldb, batched via (z/bDiv)*bOuter + (z%bDiv)*bInner
//   C: [M,N] ldc, batched via (z/bDiv)*cOuter + (z%bDiv)*cInner
//   bias: per-col (nullptr ok); res: [M,N] ldres (non-batched use only)
//   ACT: 0 = none, 1 = gelu
// ---------------------------------------------------------------------------
template <int BM, int BN, int BK, int TM, int TN, int ACT>
__global__ void __launch_bounds__((BM/TM)*(BN/TN))
gemm_kernel(int M, int N, int K,
            const float* __restrict__ A, int lda, long long strideA,
            const float* __restrict__ Bmat, int ldb, long long bOuter,
            long long bInner, int bDiv,
            float* __restrict__ Cmat, int ldc, long long cOuter, long long cInner,
            const float* __restrict__ bias,
            const float* __restrict__ res, int ldres) {
    constexpr int THREADS = (BM / TM) * (BN / TN);

    int z  = blockIdx.z;
    long long zo = z / bDiv;
    long long zi = z % bDiv;
    const float* Ab = A    + (long long)z * strideA;
    const float* Bb = Bmat + zo * bOuter + zi * bInner;
    float*       Cb = Cmat + zo * cOuter + zi * cInner;

    int tile_n = blockIdx.x * BN;
    int tile_m = blockIdx.y * BM;

    __shared__ float As[BK][BM];
    __shared__ float Bs[BK][BN];

    int tid  = threadIdx.x;
    int tcol = tid % (BN / TN);
    int trow = tid / (BN / TN);

    float acc[TM][TN];
    #pragma unroll
    for (int i = 0; i < TM; i++)
        #pragma unroll
        for (int j = 0; j < TN; j++) acc[i][j] = 0.0f;

    for (int k0 = 0; k0 < K; k0 += BK) {
        // Load A tile [BM x BK], store transposed into As[BK][BM]
        #pragma unroll
        for (int i = tid; i < BM * BK / 4; i += THREADS) {
            int r  = i / (BK / 4);
            int c4 = (i % (BK / 4)) * 4;
            float4 v = *(const float4*)&Ab[(long long)(tile_m + r) * lda + k0 + c4];
            As[c4 + 0][r] = v.x; As[c4 + 1][r] = v.y;
            As[c4 + 2][r] = v.z; As[c4 + 3][r] = v.w;
        }
        // Load B tile [BK x BN] row-major
        #pragma unroll
        for (int i = tid; i < BK * BN / 4; i += THREADS) {
            int r  = i / (BN / 4);
            int c4 = (i % (BN / 4)) * 4;
            *(float4*)&Bs[r][c4] =
                *(const float4*)&Bb[(long long)(k0 + r) * ldb + tile_n + c4];
        }
        __syncthreads();

        #pragma unroll
        for (int kk = 0; kk < BK; kk++) {
            float ra[TM], rb[TN];
            #pragma unroll
            for (int i = 0; i < TM; i += 4)
                *(float4*)&ra[i] = *(const float4*)&As[kk][trow * TM + i];
            #pragma unroll
            for (int j = 0; j < TN; j += 4)
                *(float4*)&rb[j] = *(const float4*)&Bs[kk][tcol * TN + j];
            #pragma unroll
            for (int i = 0; i < TM; i++)
                #pragma unroll
                for (int j = 0; j < TN; j++)
                    acc[i][j] = fmaf(ra[i], rb[j], acc[i][j]);
        }
        __syncthreads();
    }

    #pragma unroll
    for (int i = 0; i < TM; i++) {
        int gm = tile_m + trow * TM + i;
        #pragma unroll
        for (int j = 0; j < TN; j++) {
            int gn = tile_n + tcol * TN + j;
            float v = acc[i][j];
            if (bias) v += bias[gn];
            if (ACT == 1) v = gelu_exact(v);
            if (res) v += res[(long long)gm * ldres + gn];
            Cb[(long long)gm * ldc + gn] = v;
        }
    }
}

// ---------------------------------------------------------------------------
// Attention scores: S[z][t][s] = scale * sum_d Q[t,d]*K[s,d], z = b*12 + h
// 64x64 output tile per block, 4x4 per thread (interleaved map), full D=64.
// ---------------------------------------------------------------------------
__global__ void __launch_bounds__(256)
score_kernel(const float* __restrict__ qkv, float* __restrict__ S) {
    int z = blockIdx.z;
    int b = z / HH, h = z % HH;
    int t0 = blockIdx.y * 64;
    int s0 = blockIdx.x * 64;

    const float* Qb = qkv + (long long)b * TT * QKVN + h * DD;
    const float* Kb = Qb + CC;  // k block at col offset 768

    __shared__ float Qs[64][68];
    __shared__ float Ks[64][68];

    int tid = threadIdx.x;
    // load both tiles: 64 rows x 16 float4 each
    for (int i = tid; i < 64 * 16; i += 256) {
        int r  = i / 16;
        int c4 = (i % 16) * 4;
        float4 q = *(const float4*)&Qb[(long long)(t0 + r) * QKVN + c4];
        Qs[r][c4 + 0] = q.x; Qs[r][c4 + 1] = q.y; Qs[r][c4 + 2] = q.z; Qs[r][c4 + 3] = q.w;
        float4 k = *(const float4*)&Kb[(long long)(s0 + r) * QKVN + c4];
        Ks[r][c4 + 0] = k.x; Ks[r][c4 + 1] = k.y; Ks[r][c4 + 2] = k.z; Ks[r][c4 + 3] = k.w;
    }
    __syncthreads();

    int tx = tid % 16;   // key-col group
    int ty = tid / 16;   // query-row group
    float acc[4][4] = {};

    #pragma unroll
    for (int d4 = 0; d4 < DD; d4 += 4) {
        float4 q[4], k[4];
        #pragma unroll
        for (int i = 0; i < 4; i++) q[i] = *(const float4*)&Qs[ty + 16 * i][d4];
        #pragma unroll
        for (int j = 0; j < 4; j++) k[j] = *(const float4*)&Ks[tx + 16 * j][d4];
        #pragma unroll
        for (int i = 0; i < 4; i++)
            #pragma unroll
            for (int j = 0; j < 4; j++) {
                acc[i][j] = fmaf(q[i].x, k[j].x, acc[i][j]);
                acc[i][j] = fmaf(q[i].y, k[j].y, acc[i][j]);
                acc[i][j] = fmaf(q[i].z, k[j].z, acc[i][j]);
                acc[i][j] = fmaf(q[i].w, k[j].w, acc[i][j]);
            }
    }

    float* Sp = S + (long long)z * TT * TT;
    float scale = c_scale;
    #pragma unroll
    for (int i = 0; i < 4; i++) {
        long long rbase = (long long)(t0 + ty + 16 * i) * TT + s0;
        #pragma unroll
        for (int j = 0; j < 4; j++)
            Sp[rbase + tx + 16 * j] = acc[i][j] * scale;
    }
}

// ---------------------------------------------------------------------------
// Row softmax over T=2048 elements, one block (256 thr) per row
// ---------------------------------------------------------------------------
__global__ void __launch_bounds__(256)
softmax_kernel(float* __restrict__ S) {
    long long row = blockIdx.x;
    float* p = S + row * TT;
    int tid = threadIdx.x;

    float v[8];
    float m = -1e30f;
    #pragma unroll
    for (int i = 0; i < 8; i++) { v[i] = p[i * 256 + tid]; m = fmaxf(m, v[i]); }

    __shared__ float sh[256];
    sh[tid] = m; __syncthreads();
    #pragma unroll
    for (int o = 128; o > 0; o >>= 1) {
        if (tid < o) sh[tid] = fmaxf(sh[tid], sh[tid + o]);
        __syncthreads();
    }
    float M = sh[0];
    __syncthreads();

    float s = 0.0f;
    #pragma unroll
    for (int i = 0; i < 8; i++) { v[i] = expf(v[i] - M); s += v[i]; }
    sh[tid] = s; __syncthreads();
    #pragma unroll
    for (int o = 128; o > 0; o >>= 1) {
        if (tid < o) sh[tid] += sh[tid + o];
        __syncthreads();
    }
    float inv = 1.0f / sh[0];
    #pragma unroll
    for (int i = 0; i < 8; i++) p[i * 256 + tid] = v[i] * inv;
}

// ---------------------------------------------------------------------------
// kernel_launch
// in order: x, Wq, Wk, Wv, Wo, bo, ln1_g, ln1_b, ln2_g, ln2_b, W1, b1, W2, b2
// ---------------------------------------------------------------------------
extern "C" void kernel_launch(void* const* d_in, const int* in_sizes, int n_in,
                              void* d_out, int out_size) {
    const float* x    = (const float*)d_in[0];
    const float* Wq   = (const float*)d_in[1];
    const float* Wk   = (const float*)d_in[2];
    const float* Wv   = (const float*)d_in[3];
    const float* Wo   = (const float*)d_in[4];
    const float* bo   = (const float*)d_in[5];
    const float* ln1g = (const float*)d_in[6];
    const float* ln1b = (const float*)d_in[7];
    const float* ln2g = (const float*)d_in[8];
    const float* ln2b = (const float*)d_in[9];
    const float* W1   = (const float*)d_in[10];
    const float* b1   = (const float*)d_in[11];
    const float* W2   = (const float*)d_in[12];
    const float* b2   = (const float*)d_in[13];
    float* out = (float*)d_out;

    float *xn, *wqkv, *qkv, *S, *attn, *x2, *y, *h1;
    cudaGetSymbolAddress((void**)&xn,   g_xn);
    cudaGetSymbolAddress((void**)&wqkv, g_wqkv);
    cudaGetSymbolAddress((void**)&qkv,  g_qkv);
    cudaGetSymbolAddress((void**)&S,    g_S);
    cudaGetSymbolAddress((void**)&attn, g_attn);
    cudaGetSymbolAddress((void**)&x2,   g_x2);
    cudaGetSymbolAddress((void**)&y,    g_y);
    cudaGetSymbolAddress((void**)&h1,   g_h1);

    // 1) repack qkv weights -> [C, 3C]
    repack_kernel<<<(CC * QKVN + 255) / 256, 256>>>(Wq, Wk, Wv, wqkv);

    // 2) LN1
    ln_kernel<<<MR, 256>>>(x, ln1g, ln1b, xn);

    // 3) QKV GEMM: [8192,768] x [768,2304] -> qkv
    gemm_kernel<128, 128, 8, 8, 8, 0><<<dim3(QKVN / 128, MR / 128, 1), 256>>>(
        MR, QKVN, CC,
        xn, CC, 0,
        wqkv, QKVN, 0, 0, 1,
        qkv, QKVN, 0, 0,
        nullptr, nullptr, 0);

    // 4) scores: S = scale * Q K^T  (48 batches)
    score_kernel<<<dim3(TT / 64, TT / 64, NBH), 256>>>(qkv, S);

    // 5) softmax rows
    softmax_kernel<<<NBH * TT, 256>>>(S);

    // 6) attn = P V, written straight into head-concat [B,T,768] layout
    gemm_kernel<128, 64, 8, 8, 4, 0><<<dim3(1, TT / 128, NBH), 256>>>(
        TT, DD, TT,
        S, TT, (long long)TT * TT,
        qkv + 2 * CC, QKVN, (long long)TT * QKVN, DD, HH,
        attn, CC, (long long)TT * CC, DD,
        nullptr, nullptr, 0);

    // 7) sa = attn @ Wo + bo;  x2 = sa + x
    gemm_kernel<128, 128, 8, 8, 8, 0><<<dim3(CC / 128, MR / 128, 1), 256>>>(
        MR, CC, CC,
        attn, CC, 0,
        Wo, CC, 0, 0, 1,
        x2, CC, 0, 0,
        bo, x, CC);

    // 8) LN2
    ln_kernel<<<MR, 256>>>(x2, ln2g, ln2b, y);

    // 9) h1 = gelu(y @ W1 + b1)
    gemm_kernel<128, 128, 8, 8, 8, 1><<<dim3(MLPD / 128, MR / 128, 1), 256>>>(
        MR, MLPD, CC,
        y, CC, 0,
        W1, MLPD, 0, 0, 1,
        h1, MLPD, 0, 0,
        b1, nullptr, 0);

    // 10) out = x2 + (h1 @ W2 + b2)
    gemm_kernel<128, 128, 8, 8, 8, 0><<<dim3(CC / 128, MR / 128, 1), 256>>>(
        MR, CC, MLPD,
        h1, MLPD, 0,
        W2, CC, 0, 0, 1,
        out, CC, 0, 0,
        b2, x2, CC);
}

// round 2
// speedup vs baseline: 2.9077x; 2.9077x over previous
#include <cuda_runtime.h>
#include <cstdint>
#include <math.h>

// ---------------------------------------------------------------------------
// Problem constants
// ---------------------------------------------------------------------------
#define BB   4
#define TT   2048
#define CC   768
#define HH   12
#define DD   64
#define MLPD 3072
#define MR   (BB*TT)        /* 8192 */
#define QKVN (3*CC)         /* 2304 */
#define NBH  (BB*HH)        /* 48 */

// ---------------------------------------------------------------------------
// Scratch (device globals; no allocation allowed)
// ---------------------------------------------------------------------------
__device__ float g_xn  [MR * CC];
__device__ float g_wqkv[CC * QKVN];
__device__ float g_qkv [MR * QKVN];
__device__ float g_S   [(long long)NBH * TT * TT];
__device__ float g_attn[MR * CC];
__device__ float g_x2  [MR * CC];
__device__ float g_y   [MR * CC];
__device__ float g_h1  [MR * MLPD];

// ---------------------------------------------------------------------------
// Repack Wq/Wk/Wv [H,C,D] -> row-major [C, 3C]
// ---------------------------------------------------------------------------
__global__ void repack_kernel(const float* __restrict__ Wq,
                              const float* __restrict__ Wk,
                              const float* __restrict__ Wv,
                              float* __restrict__ out) {
    int i = blockIdx.x * 256 + threadIdx.x;
    if (i >= CC * QKVN) return;
    int c  = i / QKVN;
    int n  = i % QKVN;
    int s  = n / CC;
    int hd = n % CC;
    int h  = hd / DD;
    int d  = hd % DD;
    const float* W = (s == 0) ? Wq : ((s == 1) ? Wk : Wv);
    out[i] = W[((long long)h * CC + c) * DD + d];
}

// ---------------------------------------------------------------------------
// LayerNorm: block per row, 256 threads, C=768
// ---------------------------------------------------------------------------
__global__ void ln_kernel(const float* __restrict__ x,
                          const float* __restrict__ g,
                          const float* __restrict__ b,
                          float* __restrict__ out) {
    int row = blockIdx.x;
    int tid = threadIdx.x;
    const float* xr = x + (long long)row * CC;
    float* orow = out + (long long)row * CC;

    float v0 = xr[tid], v1 = xr[tid + 256], v2 = xr[tid + 512];
    float s  = v0 + v1 + v2;
    float s2 = v0 * v0 + v1 * v1 + v2 * v2;

    __shared__ float sh1[256], sh2[256];
    sh1[tid] = s; sh2[tid] = s2;
    __syncthreads();
    #pragma unroll
    for (int o = 128; o > 0; o >>= 1) {
        if (tid < o) { sh1[tid] += sh1[tid + o]; sh2[tid] += sh2[tid + o]; }
        __syncthreads();
    }
    float mean = sh1[0] * (1.0f / CC);
    float var  = sh2[0] * (1.0f / CC) - mean * mean;
    float rstd = rsqrtf(var + 1e-6f);

    orow[tid]       = (v0 - mean) * rstd * g[tid]       + b[tid];
    orow[tid + 256] = (v1 - mean) * rstd * g[tid + 256] + b[tid + 256];
    orow[tid + 512] = (v2 - mean) * rstd * g[tid + 512] + b[tid + 512];
}

__device__ __forceinline__ float gelu_exact(float v) {
    return 0.5f * v * (1.0f + erff(v * 0.70710678118654752f));
}

// ---------------------------------------------------------------------------
// cp.async helpers
// ---------------------------------------------------------------------------
__device__ __forceinline__ void cp16(uint32_t dst, const void* src) {
    asm volatile("cp.async.cg.shared.global [%0], [%1], 16;\n" :: "r"(dst), "l"(src));
}
__device__ __forceinline__ uint32_t f2tf32(float v) {
    uint32_t u;
    asm("cvt.rna.tf32.f32 %0, %1;\n" : "=r"(u) : "f"(v));
    return u;
}
__device__ __forceinline__ void mma_tf32(float& c0, float& c1, float& c2, float& c3,
                                         uint32_t a0, uint32_t a1, uint32_t a2, uint32_t a3,
                                         uint32_t b0, uint32_t b1) {
    asm volatile("mma.sync.aligned.m16n8k8.row.col.f32.tf32.tf32.f32 "
                 "{%0,%1,%2,%3}, {%4,%5,%6,%7}, {%8,%9}, {%0,%1,%2,%3};\n"
                 : "+f"(c0), "+f"(c1), "+f"(c2), "+f"(c3)
                 : "r"(a0), "r"(a1), "r"(a2), "r"(a3), "r"(b0), "r"(b1));
}

// ---------------------------------------------------------------------------
// Tensor-core tf32 GEMM: C = act(alpha*A*B + bias) + res
//   A: [M,K] row-major, batch offset zo*aO + zi*aI  (z = blockIdx.z, zo=z/zdiv, zi=z%zdiv)
//   B: TRANSB=0: [K,N] row-major;  TRANSB=1: [N,K] row-major (i.e. computes A*B^T)
//   C: [M,N], batch offset zo*cO + zi*cI
//   8 warps: 2x4 grid of 64 x (BN/4) warp tiles; m16n8k8 tf32 mma
// ---------------------------------------------------------------------------
template <int BM, int BN, int BK, int TRANSB, int ACT>
__global__ void __launch_bounds__(256)
gemm_tc(int M, int N, int K,
        const float* __restrict__ A, int lda, long long aO, long long aI,
        const float* __restrict__ B, int ldb, long long bO, long long bI,
        float* __restrict__ C, int ldc, long long cO, long long cI,
        int zdiv, float alpha,
        const float* __restrict__ bias,
        const float* __restrict__ res, int ldres) {
    constexpr int WM = 64, WN = BN / 4;
    constexpr int MT = WM / 16, NT = WN / 8;
    constexpr int ASTR = BK + 4;                       // bank: 4g+t bijective
    constexpr int BSTR = TRANSB ? (BK + 4) : (BN + 8); // bank: 4g+t / 8t+g bijective
    constexpr int ASTAGE = BM * ASTR;
    constexpr int BSTAGE = TRANSB ? BN * BSTR : BK * BSTR;

    extern __shared__ float sm[];
    float* As = sm;
    float* Bs = sm + 2 * ASTAGE;

    int z = blockIdx.z;
    long long zo = z / zdiv, zi = z % zdiv;
    const float* Ab = A + zo * aO + zi * aI;
    const float* Bb = B + zo * bO + zi * bI;
    float*       Cb = C + zo * cO + zi * cI;

    int tile_m = blockIdx.y * BM, tile_n = blockIdx.x * BN;
    int tid = threadIdx.x;
    int wid = tid >> 5, lane = tid & 31;
    int warp_m = wid >> 2, warp_n = wid & 3;
    int g = lane >> 2, t = lane & 3;

    uint32_t as_base = (uint32_t)__cvta_generic_to_shared(As);
    uint32_t bs_base = (uint32_t)__cvta_generic_to_shared(Bs);

    float acc[MT][NT][4];
    #pragma unroll
    for (int i = 0; i < MT; i++)
        #pragma unroll
        for (int j = 0; j < NT; j++)
            #pragma unroll
            for (int l = 0; l < 4; l++) acc[i][j][l] = 0.0f;

    auto load_tiles = [&](int st, int k0) {
        #pragma unroll
        for (int idx = tid; idx < BM * BK / 4; idx += 256) {
            int r = idx / (BK / 4);
            int c = (idx % (BK / 4)) * 4;
            cp16(as_base + (uint32_t)((st * BM + r) * ASTR + c) * 4,
                 Ab + (long long)(tile_m + r) * lda + k0 + c);
        }
        if (TRANSB) {
            #pragma unroll
            for (int idx = tid; idx < BN * BK / 4; idx += 256) {
                int r = idx / (BK / 4);
                int c = (idx % (BK / 4)) * 4;
                cp16(bs_base + (uint32_t)((st * BN + r) * BSTR + c) * 4,
                     Bb + (long long)(tile_n + r) * ldb + k0 + c);
            }
        } else {
            #pragma unroll
            for (int idx = tid; idx < BK * BN / 4; idx += 256) {
                int r = idx / (BN / 4);
                int c = (idx % (BN / 4)) * 4;
                cp16(bs_base + (uint32_t)((st * BK + r) * BSTR + c) * 4,
                     Bb + (long long)(k0 + r) * ldb + tile_n + c);
            }
        }
    };

    load_tiles(0, 0);
    asm volatile("cp.async.commit_group;\n");

    int nK = K / BK;
    for (int kt = 0; kt < nK; kt++) {
        if (kt + 1 < nK) {
            load_tiles((kt + 1) & 1, (kt + 1) * BK);
            asm volatile("cp.async.commit_group;\n");
            asm volatile("cp.async.wait_group 1;\n");
        } else {
            asm volatile("cp.async.wait_group 0;\n");
        }
        __syncthreads();

        int st = kt & 1;
        const float* Ast = As + st * ASTAGE;
        const float* Bst = Bs + st * BSTAGE;

        #pragma unroll
        for (int ks = 0; ks < BK / 8; ks++) {
            uint32_t af[MT][4];
            #pragma unroll
            for (int mt = 0; mt < MT; mt++) {
                int r = warp_m * WM + mt * 16 + g;
                int c = ks * 8 + t;
                af[mt][0] = f2tf32(Ast[(r    ) * ASTR + c    ]);
                af[mt][1] = f2tf32(Ast[(r + 8) * ASTR + c    ]);
                af[mt][2] = f2tf32(Ast[(r    ) * ASTR + c + 4]);
                af[mt][3] = f2tf32(Ast[(r + 8) * ASTR + c + 4]);
            }
            uint32_t bf[NT][2];
            #pragma unroll
            for (int nt = 0; nt < NT; nt++) {
                if (TRANSB) {
                    int n = warp_n * WN + nt * 8 + g;
                    bf[nt][0] = f2tf32(Bst[n * BSTR + ks * 8 + t    ]);
                    bf[nt][1] = f2tf32(Bst[n * BSTR + ks * 8 + t + 4]);
                } else {
                    int n = warp_n * WN + nt * 8 + g;
                    bf[nt][0] = f2tf32(Bst[(ks * 8 + t    ) * BSTR + n]);
                    bf[nt][1] = f2tf32(Bst[(ks * 8 + t + 4) * BSTR + n]);
                }
            }
            #pragma unroll
            for (int mt = 0; mt < MT; mt++)
                #pragma unroll
                for (int nt = 0; nt < NT; nt++)
                    mma_tf32(acc[mt][nt][0], acc[mt][nt][1], acc[mt][nt][2], acc[mt][nt][3],
                             af[mt][0], af[mt][1], af[mt][2], af[mt][3],
                             bf[nt][0], bf[nt][1]);
        }
        __syncthreads();
    }

    // epilogue: c0,c1 at (gm, gn..gn+1); c2,c3 at (gm+8, gn..gn+1)
    #pragma unroll
    for (int mt = 0; mt < MT; mt++) {
        #pragma unroll
        for (int nt = 0; nt < NT; nt++) {
            int gm = tile_m + warp_m * WM + mt * 16 + g;
            int gn = tile_n + warp_n * WN + nt * 8 + t * 2;
            float v0 = acc[mt][nt][0] * alpha;
            float v1 = acc[mt][nt][1] * alpha;
            float v2 = acc[mt][nt][2] * alpha;
            float v3 = acc[mt][nt][3] * alpha;
            if (bias) {
                float2 bb = *(const float2*)&bias[gn];
                v0 += bb.x; v1 += bb.y; v2 += bb.x; v3 += bb.y;
            }
            if (ACT == 1) {
                v0 = gelu_exact(v0); v1 = gelu_exact(v1);
                v2 = gelu_exact(v2); v3 = gelu_exact(v3);
            }
            if (res) {
                float2 r0 = *(const float2*)&res[(long long)gm * ldres + gn];
                float2 r1 = *(const float2*)&res[(long long)(gm + 8) * ldres + gn];
                v0 += r0.x; v1 += r0.y; v2 += r1.x; v3 += r1.y;
            }
            *(float2*)&Cb[(long long)gm * ldc + gn]       = make_float2(v0, v1);
            *(float2*)&Cb[(long long)(gm + 8) * ldc + gn] = make_float2(v2, v3);
        }
    }
}

// ---------------------------------------------------------------------------
// Row softmax over T=2048, block (256 thr) per row, float4 vectorized
// ---------------------------------------------------------------------------
__global__ void __launch_bounds__(256)
softmax_kernel(float* __restrict__ S) {
    long long row = blockIdx.x;
    float4* p = (float4*)(S + row * TT);
    int tid = threadIdx.x;

    float4 u0 = p[tid], u1 = p[tid + 256];
    float m = fmaxf(fmaxf(fmaxf(u0.x, u0.y), fmaxf(u0.z, u0.w)),
                    fmaxf(fmaxf(u1.x, u1.y), fmaxf(u1.z, u1.w)));

    __shared__ float sh[256];
    sh[tid] = m; __syncthreads();
    #pragma unroll
    for (int o = 128; o > 0; o >>= 1) {
        if (tid < o) sh[tid] = fmaxf(sh[tid], sh[tid + o]);
        __syncthreads();
    }
    float M = sh[0];
    __syncthreads();

    u0.x = expf(u0.x - M); u0.y = expf(u0.y - M);
    u0.z = expf(u0.z - M); u0.w = expf(u0.w - M);
    u1.x = expf(u1.x - M); u1.y = expf(u1.y - M);
    u1.z = expf(u1.z - M); u1.w = expf(u1.w - M);
    float s = u0.x + u0.y + u0.z + u0.w + u1.x + u1.y + u1.z + u1.w;

    sh[tid] = s; __syncthreads();
    #pragma unroll
    for (int o = 128; o > 0; o >>= 1) {
        if (tid < o) sh[tid] += sh[tid + o];
        __syncthreads();
    }
    float inv = 1.0f / sh[0];
    u0.x *= inv; u0.y *= inv; u0.z *= inv; u0.w *= inv;
    u1.x *= inv; u1.y *= inv; u1.z *= inv; u1.w *= inv;
    p[tid] = u0; p[tid + 256] = u1;
}

// ---------------------------------------------------------------------------
// kernel_launch
// ---------------------------------------------------------------------------
extern "C" void kernel_launch(void* const* d_in, const int* in_sizes, int n_in,
                              void* d_out, int out_size) {
    const float* x    = (const float*)d_in[0];
    const float* Wq   = (const float*)d_in[1];
    const float* Wk   = (const float*)d_in[2];
    const float* Wv   = (const float*)d_in[3];
    const float* Wo   = (const float*)d_in[4];
    const float* bo   = (const float*)d_in[5];
    const float* ln1g = (const float*)d_in[6];
    const float* ln1b = (const float*)d_in[7];
    const float* ln2g = (const float*)d_in[8];
    const float* ln2b = (const float*)d_in[9];
    const float* W1   = (const float*)d_in[10];
    const float* b1   = (const float*)d_in[11];
    const float* W2   = (const float*)d_in[12];
    const float* b2   = (const float*)d_in[13];
    float* out = (float*)d_out;

    float *xn, *wqkv, *qkv, *S, *attn, *x2, *y, *h1;
    cudaGetSymbolAddress((void**)&xn,   g_xn);
    cudaGetSymbolAddress((void**)&wqkv, g_wqkv);
    cudaGetSymbolAddress((void**)&qkv,  g_qkv);
    cudaGetSymbolAddress((void**)&S,    g_S);
    cudaGetSymbolAddress((void**)&attn, g_attn);
    cudaGetSymbolAddress((void**)&x2,   g_x2);
    cudaGetSymbolAddress((void**)&y,    g_y);
    cudaGetSymbolAddress((void**)&h1,   g_h1);

    // smem sizes per instantiation
    const int SM_DENSE = (2 * 128 * 36 + 2 * 32 * 136) * 4;  // 71680
    const int SM_SCORE = (2 * 128 * 36 + 2 * 128 * 36) * 4;  // 73728
    const int SM_PV    = (2 * 128 * 36 + 2 * 32 * 72) * 4;   // 55296

    cudaFuncSetAttribute(gemm_tc<128,128,32,0,0>, cudaFuncAttributeMaxDynamicSharedMemorySize, SM_DENSE);
    cudaFuncSetAttribute(gemm_tc<128,128,32,0,1>, cudaFuncAttributeMaxDynamicSharedMemorySize, SM_DENSE);
    cudaFuncSetAttribute(gemm_tc<128,128,32,1,0>, cudaFuncAttributeMaxDynamicSharedMemorySize, SM_SCORE);
    cudaFuncSetAttribute(gemm_tc<128, 64,32,0,0>, cudaFuncAttributeMaxDynamicSharedMemorySize, SM_PV);

    const float SCALE = 0.03608439182435161f;  // 768^-0.5

    // 1) repack qkv weights
    repack_kernel<<<(CC * QKVN + 255) / 256, 256>>>(Wq, Wk, Wv, wqkv);

    // 2) LN1
    ln_kernel<<<MR, 256>>>(x, ln1g, ln1b, xn);

    // 3) QKV GEMM: [8192,768] x [768,2304]
    gemm_tc<128,128,32,0,0><<<dim3(QKVN/128, MR/128, 1), 256, SM_DENSE>>>(
        MR, QKVN, CC,
        xn, CC, 0, 0,
        wqkv, QKVN, 0, 0,
        qkv, QKVN, 0, 0,
        1, 1.0f, nullptr, nullptr, 0);

    // 4) scores: S = SCALE * Q K^T (48 batches, B = K stored [N,K] -> TRANSB)
    gemm_tc<128,128,32,1,0><<<dim3(TT/128, TT/128, NBH), 256, SM_SCORE>>>(
        TT, TT, DD,
        qkv, QKVN, (long long)TT * QKVN, DD,
        qkv + CC, QKVN, (long long)TT * QKVN, DD,
        S, TT, (long long)HH * TT * TT, (long long)TT * TT,
        HH, SCALE, nullptr, nullptr, 0);

    // 5) softmax rows
    softmax_kernel<<<NBH * TT, 256>>>(S);

    // 6) attn = P V, straight into head-concat [B,T,768]
    gemm_tc<128,64,32,0,0><<<dim3(1, TT/128, NBH), 256, SM_PV>>>(
        TT, DD, TT,
        S, TT, (long long)HH * TT * TT, (long long)TT * TT,
        qkv + 2 * CC, QKVN, (long long)TT * QKVN, DD,
        attn, CC, (long long)TT * CC, DD,
        HH, 1.0f, nullptr, nullptr, 0);

    // 7) x2 = attn @ Wo + bo + x
    gemm_tc<128,128,32,0,0><<<dim3(CC/128, MR/128, 1), 256, SM_DENSE>>>(
        MR, CC, CC,
        attn, CC, 0, 0,
        Wo, CC, 0, 0,
        x2, CC, 0, 0,
        1, 1.0f, bo, x, CC);

    // 8) LN2
    ln_kernel<<<MR, 256>>>(x2, ln2g, ln2b, y);

    // 9) h1 = gelu(y @ W1 + b1)
    gemm_tc<128,128,32,0,1><<<dim3(MLPD/128, MR/128, 1), 256, SM_DENSE>>>(
        MR, MLPD, CC,
        y, CC, 0, 0,
        W1, MLPD, 0, 0,
        h1, MLPD, 0, 0,
        1, 1.0f, b1, nullptr, 0);

    // 10) out = x2 + (h1 @ W2 + b2)
    gemm_tc<128,128,32,0,0><<<dim3(CC/128, MR/128, 1), 256, SM_DENSE>>>(
        MR, CC, MLPD,
        h1, MLPD, 0, 0,
        W2, CC, 0, 0,
        out, CC, 0, 0,
        1, 1.0f, b2, x2, CC);
}

// round 3
// speedup vs baseline: 3.9094x; 1.3445x over previous
#include <cuda_runtime.h>
#include <cstdint>
#include <math.h>

// ---------------------------------------------------------------------------
// Problem constants
// ---------------------------------------------------------------------------
#define BB   4
#define TT   2048
#define CC   768
#define HH   12
#define DD   64
#define MLPD 3072
#define MR   (BB*TT)        /* 8192 */
#define QKVN (3*CC)         /* 2304 */
#define NBH  (BB*HH)        /* 48 */

#define SCALE_F 0.03608439182435161f  /* 768^-0.5 */

// ---------------------------------------------------------------------------
// Scratch (device globals; no allocation allowed)
// ---------------------------------------------------------------------------
__device__ float g_xn  [MR * CC];
__device__ float g_wqkv[CC * QKVN];
__device__ float g_qkv [MR * QKVN];
__device__ float g_attn[MR * CC];
__device__ float g_x2  [MR * CC];
__device__ float g_y   [MR * CC];
__device__ float g_h1  [MR * MLPD];
__device__ float g_wor [CC * CC];
__device__ float g_w1r [CC * MLPD];
__device__ float g_w2r [MLPD * CC];

// ---------------------------------------------------------------------------
// Helpers
// ---------------------------------------------------------------------------
__device__ __forceinline__ void cp16(uint32_t dst, const void* src) {
    asm volatile("cp.async.cg.shared.global [%0], [%1], 16;\n" :: "r"(dst), "l"(src));
}
__device__ __forceinline__ uint32_t f2tf32(float v) {
    uint32_t u;
    asm("cvt.rna.tf32.f32 %0, %1;\n" : "=r"(u) : "f"(v));
    return u;
}
__device__ __forceinline__ float tf32r(float v) {
    return __uint_as_float(f2tf32(v));
}
__device__ __forceinline__ void mma_tf32(float& c0, float& c1, float& c2, float& c3,
                                         uint32_t a0, uint32_t a1, uint32_t a2, uint32_t a3,
                                         uint32_t b0, uint32_t b1) {
    asm volatile("mma.sync.aligned.m16n8k8.row.col.f32.tf32.tf32.f32 "
                 "{%0,%1,%2,%3}, {%4,%5,%6,%7}, {%8,%9}, {%0,%1,%2,%3};\n"
                 : "+f"(c0), "+f"(c1), "+f"(c2), "+f"(c3)
                 : "r"(a0), "r"(a1), "r"(a2), "r"(a3), "r"(b0), "r"(b1));
}
__device__ __forceinline__ float gelu_exact(float v) {
    return 0.5f * v * (1.0f + erff(v * 0.70710678118654752f));
}

// ---------------------------------------------------------------------------
// Pre-round an fp32 array to tf32 bit patterns
// ---------------------------------------------------------------------------
__global__ void round_kernel(const float* __restrict__ in, float* __restrict__ out, int n) {
    int i = blockIdx.x * 256 + threadIdx.x;
    if (i < n) out[i] = tf32r(in[i]);
}

// ---------------------------------------------------------------------------
// Repack Wq/Wk/Wv [H,C,D] -> row-major [C, 3C], tf32 pre-rounded
// ---------------------------------------------------------------------------
__global__ void repack_kernel(const float* __restrict__ Wq,
                              const float* __restrict__ Wk,
                              const float* __restrict__ Wv,
                              float* __restrict__ out) {
    int i = blockIdx.x * 256 + threadIdx.x;
    if (i >= CC * QKVN) return;
    int c  = i / QKVN;
    int n  = i % QKVN;
    int s  = n / CC;
    int hd = n % CC;
    int h  = hd / DD;
    int d  = hd % DD;
    const float* W = (s == 0) ? Wq : ((s == 1) ? Wk : Wv);
    out[i] = tf32r(W[((long long)h * CC + c) * DD + d]);
}

// ---------------------------------------------------------------------------
// LayerNorm: block per row, 256 threads, C=768; output tf32 pre-rounded
// ---------------------------------------------------------------------------
__global__ void ln_kernel(const float* __restrict__ x,
                          const float* __restrict__ g,
                          const float* __restrict__ b,
                          float* __restrict__ out) {
    int row = blockIdx.x;
    int tid = threadIdx.x;
    const float* xr = x + (long long)row * CC;
    float* orow = out + (long long)row * CC;

    float v0 = xr[tid], v1 = xr[tid + 256], v2 = xr[tid + 512];
    float s  = v0 + v1 + v2;
    float s2 = v0 * v0 + v1 * v1 + v2 * v2;

    __shared__ float sh1[256], sh2[256];
    sh1[tid] = s; sh2[tid] = s2;
    __syncthreads();
    #pragma unroll
    for (int o = 128; o > 0; o >>= 1) {
        if (tid < o) { sh1[tid] += sh1[tid + o]; sh2[tid] += sh2[tid + o]; }
        __syncthreads();
    }
    float mean = sh1[0] * (1.0f / CC);
    float var  = sh2[0] * (1.0f / CC) - mean * mean;
    float rstd = rsqrtf(var + 1e-6f);

    orow[tid]       = tf32r((v0 - mean) * rstd * g[tid]       + b[tid]);
    orow[tid + 256] = tf32r((v1 - mean) * rstd * g[tid + 256] + b[tid + 256]);
    orow[tid + 512] = tf32r((v2 - mean) * rstd * g[tid + 512] + b[tid + 512]);
}

// ---------------------------------------------------------------------------
// Tensor-core tf32 GEMM: C = act(A*B + bias) + res  (inputs pre-rounded tf32)
//   A: [M,K] row-major;  B: [K,N] row-major;  C: [M,N]
//   8 warps: 2x4 grid of 64x32 warp tiles; m16n8k8 tf32 mma
//   TFOUT: round output to tf32 (for values feeding later mma)
// ---------------------------------------------------------------------------
template <int BM, int BN, int BK, int ACT, int TFOUT>
__global__ void __launch_bounds__(256)
gemm_tc(int M, int N, int K,
        const float* __restrict__ A, int lda,
        const float* __restrict__ B, int ldb,
        float* __restrict__ C, int ldc,
        const float* __restrict__ bias,
        const float* __restrict__ res, int ldres) {
    constexpr int WM = 64, WN = BN / 4;
    constexpr int MT = WM / 16, NT = WN / 8;
    constexpr int ASTR = BK + 4;
    constexpr int BSTR = BN + 8;
    constexpr int ASTAGE = BM * ASTR;
    constexpr int BSTAGE = BK * BSTR;

    extern __shared__ float sm[];
    float* As = sm;
    float* Bs = sm + 2 * ASTAGE;

    int tile_m = blockIdx.y * BM, tile_n = blockIdx.x * BN;
    int tid = threadIdx.x;
    int wid = tid >> 5, lane = tid & 31;
    int warp_m = wid >> 2, warp_n = wid & 3;
    int g = lane >> 2, t = lane & 3;

    uint32_t as_base = (uint32_t)__cvta_generic_to_shared(As);
    uint32_t bs_base = (uint32_t)__cvta_generic_to_shared(Bs);

    float acc[MT][NT][4];
    #pragma unroll
    for (int i = 0; i < MT; i++)
        #pragma unroll
        for (int j = 0; j < NT; j++)
            #pragma unroll
            for (int l = 0; l < 4; l++) acc[i][j][l] = 0.0f;

    auto load_tiles = [&](int st, int k0) {
        #pragma unroll
        for (int idx = tid; idx < BM * BK / 4; idx += 256) {
            int r = idx / (BK / 4);
            int c = (idx % (BK / 4)) * 4;
            cp16(as_base + (uint32_t)((st * BM + r) * ASTR + c) * 4,
                 A + (long long)(tile_m + r) * lda + k0 + c);
        }
        #pragma unroll
        for (int idx = tid; idx < BK * BN / 4; idx += 256) {
            int r = idx / (BN / 4);
            int c = (idx % (BN / 4)) * 4;
            cp16(bs_base + (uint32_t)((st * BK + r) * BSTR + c) * 4,
                 B + (long long)(k0 + r) * ldb + tile_n + c);
        }
    };

    load_tiles(0, 0);
    asm volatile("cp.async.commit_group;\n");

    int nK = K / BK;
    for (int kt = 0; kt < nK; kt++) {
        if (kt + 1 < nK) {
            load_tiles((kt + 1) & 1, (kt + 1) * BK);
            asm volatile("cp.async.commit_group;\n");
            asm volatile("cp.async.wait_group 1;\n");
        } else {
            asm volatile("cp.async.wait_group 0;\n");
        }
        __syncthreads();

        int st = kt & 1;
        const float* Ast = As + st * ASTAGE;
        const float* Bst = Bs + st * BSTAGE;

        #pragma unroll
        for (int ks = 0; ks < BK / 8; ks++) {
            uint32_t af[MT][4];
            #pragma unroll
            for (int mt = 0; mt < MT; mt++) {
                int r = warp_m * WM + mt * 16 + g;
                int c = ks * 8 + t;
                af[mt][0] = __float_as_uint(Ast[(r    ) * ASTR + c    ]);
                af[mt][1] = __float_as_uint(Ast[(r + 8) * ASTR + c    ]);
                af[mt][2] = __float_as_uint(Ast[(r    ) * ASTR + c + 4]);
                af[mt][3] = __float_as_uint(Ast[(r + 8) * ASTR + c + 4]);
            }
            uint32_t bf[NT][2];
            #pragma unroll
            for (int nt = 0; nt < NT; nt++) {
                int n = warp_n * WN + nt * 8 + g;
                bf[nt][0] = __float_as_uint(Bst[(ks * 8 + t    ) * BSTR + n]);
                bf[nt][1] = __float_as_uint(Bst[(ks * 8 + t + 4) * BSTR + n]);
            }
            #pragma unroll
            for (int mt = 0; mt < MT; mt++)
                #pragma unroll
                for (int nt = 0; nt < NT; nt++)
                    mma_tf32(acc[mt][nt][0], acc[mt][nt][1], acc[mt][nt][2], acc[mt][nt][3],
                             af[mt][0], af[mt][1], af[mt][2], af[mt][3],
                             bf[nt][0], bf[nt][1]);
        }
        __syncthreads();
    }

    #pragma unroll
    for (int mt = 0; mt < MT; mt++) {
        #pragma unroll
        for (int nt = 0; nt < NT; nt++) {
            int gm = tile_m + warp_m * WM + mt * 16 + g;
            int gn = tile_n + warp_n * WN + nt * 8 + t * 2;
            float v0 = acc[mt][nt][0];
            float v1 = acc[mt][nt][1];
            float v2 = acc[mt][nt][2];
            float v3 = acc[mt][nt][3];
            if (bias) {
                float2 bb = *(const float2*)&bias[gn];
                v0 += bb.x; v1 += bb.y; v2 += bb.x; v3 += bb.y;
            }
            if (ACT == 1) {
                v0 = gelu_exact(v0); v1 = gelu_exact(v1);
                v2 = gelu_exact(v2); v3 = gelu_exact(v3);
            }
            if (res) {
                float2 r0 = *(const float2*)&res[(long long)gm * ldres + gn];
                float2 r1 = *(const float2*)&res[(long long)(gm + 8) * ldres + gn];
                v0 += r0.x; v1 += r0.y; v2 += r1.x; v3 += r1.y;
            }
            if (TFOUT) {
                v0 = tf32r(v0); v1 = tf32r(v1); v2 = tf32r(v2); v3 = tf32r(v3);
            }
            *(float2*)&C[(long long)gm * ldc + gn]       = make_float2(v0, v1);
            *(float2*)&C[(long long)(gm + 8) * ldc + gn] = make_float2(v2, v3);
        }
    }
}

// ---------------------------------------------------------------------------
// Flash attention: one block = 128 Q rows of one (b,h).
// 8 warps x 16 rows. K/V streamed in 64-key double-buffered chunks.
// Q fragments cached in registers (scaled); P staged in warp-private smem
// (reuses the Q tile region); online softmax; O accumulated via tensor cores.
// qkv is tf32 pre-rounded; attn written tf32 pre-rounded (head-concat layout).
// ---------------------------------------------------------------------------
#define QSTR 68
#define KSTR 68
#define VSTR 72
#define FSM_BYTES ((128*QSTR + 2*64*KSTR + 2*64*VSTR) * 4)

__global__ void __launch_bounds__(256)
flash_kernel(const float* __restrict__ qkv, float* __restrict__ attn) {
    extern __shared__ float sm[];
    float* QP = sm;                       // Q tile then P tiles (union)
    float* Ks = sm + 128 * QSTR;
    float* Vs = Ks + 2 * 64 * KSTR;

    int z = blockIdx.y;
    int b = z / HH, h = z % HH;
    int t0 = blockIdx.x * 128;
    const float* Qg = qkv + (long long)b * TT * QKVN + h * DD;
    const float* Kg = Qg + CC;
    const float* Vg = Qg + 2 * CC;
    float* Og = attn + ((long long)b * TT + t0) * CC + h * DD;

    int tid = threadIdx.x, wid = tid >> 5, lane = tid & 31;
    int g = lane >> 2, t = lane & 3;

    uint32_t qp_base = (uint32_t)__cvta_generic_to_shared(QP);
    uint32_t k_base  = (uint32_t)__cvta_generic_to_shared(Ks);
    uint32_t v_base  = (uint32_t)__cvta_generic_to_shared(Vs);

    // ---- load Q tile (commit as its own group) ----
    #pragma unroll
    for (int idx = tid; idx < 128 * 16; idx += 256) {
        int r = idx >> 4, c = (idx & 15) * 4;
        cp16(qp_base + (uint32_t)(r * QSTR + c) * 4,
             Qg + (long long)(t0 + r) * QKVN + c);
    }
    asm volatile("cp.async.commit_group;\n");

    auto loadKV = [&](int st, int key0) {
        #pragma unroll
        for (int idx = tid; idx < 64 * 16; idx += 256) {
            int r = idx >> 4, c = (idx & 15) * 4;
            cp16(k_base + (uint32_t)((st * 64 + r) * KSTR + c) * 4,
                 Kg + (long long)(key0 + r) * QKVN + c);
            cp16(v_base + (uint32_t)((st * 64 + r) * VSTR + c) * 4,
                 Vg + (long long)(key0 + r) * QKVN + c);
        }
    };
    loadKV(0, 0);
    asm volatile("cp.async.commit_group;\n");

    // ---- build scaled Q fragments in registers ----
    asm volatile("cp.async.wait_group 1;\n");  // Q done (KV0 may be pending)
    __syncthreads();
    uint32_t qf[8][4];
    {
        int r0 = wid * 16 + g;
        #pragma unroll
        for (int ks = 0; ks < 8; ks++) {
            int c = ks * 8 + t;
            qf[ks][0] = f2tf32(QP[(r0    ) * QSTR + c    ] * SCALE_F);
            qf[ks][1] = f2tf32(QP[(r0 + 8) * QSTR + c    ] * SCALE_F);
            qf[ks][2] = f2tf32(QP[(r0    ) * QSTR + c + 4] * SCALE_F);
            qf[ks][3] = f2tf32(QP[(r0 + 8) * QSTR + c + 4] * SCALE_F);
        }
    }
    __syncthreads();  // QP region now free for P

    float o[8][4];
    #pragma unroll
    for (int i = 0; i < 8; i++)
        #pragma unroll
        for (int l = 0; l < 4; l++) o[i][l] = 0.0f;
    float m0 = -1e30f, m1 = -1e30f, l0 = 0.0f, l1 = 0.0f;

    const int NCH = TT / 64;  // 32
    for (int j = 0; j < NCH; j++) {
        if (j + 1 < NCH) {
            loadKV((j + 1) & 1, (j + 1) * 64);
            asm volatile("cp.async.commit_group;\n");
            asm volatile("cp.async.wait_group 1;\n");
        } else {
            asm volatile("cp.async.wait_group 0;\n");
        }
        __syncthreads();

        const float* Kst = Ks + (j & 1) * 64 * KSTR;
        const float* Vst = Vs + (j & 1) * 64 * VSTR;

        // ---- S = (Q*scale) K^T : 16x64 per warp ----
        float s[8][4];
        #pragma unroll
        for (int i = 0; i < 8; i++)
            #pragma unroll
            for (int l = 0; l < 4; l++) s[i][l] = 0.0f;

        #pragma unroll
        for (int ks = 0; ks < 8; ks++) {
            #pragma unroll
            for (int nt = 0; nt < 8; nt++) {
                uint32_t b0 = __float_as_uint(Kst[(nt * 8 + g) * KSTR + ks * 8 + t    ]);
                uint32_t b1 = __float_as_uint(Kst[(nt * 8 + g) * KSTR + ks * 8 + t + 4]);
                mma_tf32(s[nt][0], s[nt][1], s[nt][2], s[nt][3],
                         qf[ks][0], qf[ks][1], qf[ks][2], qf[ks][3], b0, b1);
            }
        }

        // ---- online softmax ----
        float cm0 = -1e30f, cm1 = -1e30f;
        #pragma unroll
        for (int nt = 0; nt < 8; nt++) {
            cm0 = fmaxf(cm0, fmaxf(s[nt][0], s[nt][1]));
            cm1 = fmaxf(cm1, fmaxf(s[nt][2], s[nt][3]));
        }
        cm0 = fmaxf(cm0, __shfl_xor_sync(0xffffffff, cm0, 1));
        cm0 = fmaxf(cm0, __shfl_xor_sync(0xffffffff, cm0, 2));
        cm1 = fmaxf(cm1, __shfl_xor_sync(0xffffffff, cm1, 1));
        cm1 = fmaxf(cm1, __shfl_xor_sync(0xffffffff, cm1, 2));

        float nm0 = fmaxf(m0, cm0), nm1 = fmaxf(m1, cm1);
        float a0 = __expf(m0 - nm0), a1 = __expf(m1 - nm1);
        l0 *= a0; l1 *= a1;
        #pragma unroll
        for (int nt = 0; nt < 8; nt++) {
            o[nt][0] *= a0; o[nt][1] *= a0; o[nt][2] *= a1; o[nt][3] *= a1;
        }

        int pr = wid * 16 + g;
        float rs0 = 0.0f, rs1 = 0.0f;
        #pragma unroll
        for (int nt = 0; nt < 8; nt++) {
            float p0 = __expf(s[nt][0] - nm0);
            float p1 = __expf(s[nt][1] - nm0);
            float p2 = __expf(s[nt][2] - nm1);
            float p3 = __expf(s[nt][3] - nm1);
            rs0 += p0 + p1; rs1 += p2 + p3;
            *(float2*)&QP[(pr    ) * QSTR + nt * 8 + 2 * t] =
                make_float2(tf32r(p0), tf32r(p1));
            *(float2*)&QP[(pr + 8) * QSTR + nt * 8 + 2 * t] =
                make_float2(tf32r(p2), tf32r(p3));
        }
        rs0 += __shfl_xor_sync(0xffffffff, rs0, 1);
        rs0 += __shfl_xor_sync(0xffffffff, rs0, 2);
        rs1 += __shfl_xor_sync(0xffffffff, rs1, 1);
        rs1 += __shfl_xor_sync(0xffffffff, rs1, 2);
        l0 += rs0; l1 += rs1;
        m0 = nm0; m1 = nm1;
        __syncwarp();

        // ---- O += P V : P [16x64] x V [64x64] ----
        #pragma unroll
        for (int ks = 0; ks < 8; ks++) {
            uint32_t af0 = __float_as_uint(QP[(pr    ) * QSTR + ks * 8 + t    ]);
            uint32_t af1 = __float_as_uint(QP[(pr + 8) * QSTR + ks * 8 + t    ]);
            uint32_t af2 = __float_as_uint(QP[(pr    ) * QSTR + ks * 8 + t + 4]);
            uint32_t af3 = __float_as_uint(QP[(pr + 8) * QSTR + ks * 8 + t + 4]);
            #pragma unroll
            for (int nt = 0; nt < 8; nt++) {
                uint32_t b0 = __float_as_uint(Vst[(ks * 8 + t    ) * VSTR + nt * 8 + g]);
                uint32_t b1 = __float_as_uint(Vst[(ks * 8 + t + 4) * VSTR + nt * 8 + g]);
                mma_tf32(o[nt][0], o[nt][1], o[nt][2], o[nt][3],
                         af0, af1, af2, af3, b0, b1);
            }
        }
        __syncthreads();
    }

    // ---- epilogue: O /= l, tf32-round, write head-concat ----
    float r0 = 1.0f / l0, r1 = 1.0f / l1;
    int row = wid * 16 + g;
    #pragma unroll
    for (int nt = 0; nt < 8; nt++) {
        int cn = nt * 8 + 2 * t;
        *(float2*)&Og[(long long)(row    ) * CC + cn] =
            make_float2(tf32r(o[nt][0] * r0), tf32r(o[nt][1] * r0));
        *(float2*)&Og[(long long)(row + 8) * CC + cn] =
            make_float2(tf32r(o[nt][2] * r1), tf32r(o[nt][3] * r1));
    }
}

// ---------------------------------------------------------------------------
// kernel_launch
// ---------------------------------------------------------------------------
extern "C" void kernel_launch(void* const* d_in, const int* in_sizes, int n_in,
                              void* d_out, int out_size) {
    const float* x    = (const float*)d_in[0];
    const float* Wq   = (const float*)d_in[1];
    const float* Wk   = (const float*)d_in[2];
    const float* Wv   = (const float*)d_in[3];
    const float* Wo   = (const float*)d_in[4];
    const float* bo   = (const float*)d_in[5];
    const float* ln1g = (const float*)d_in[6];
    const float* ln1b = (const float*)d_in[7];
    const float* ln2g = (const float*)d_in[8];
    const float* ln2b = (const float*)d_in[9];
    const float* W1   = (const float*)d_in[10];
    const float* b1   = (const float*)d_in[11];
    const float* W2   = (const float*)d_in[12];
    const float* b2   = (const float*)d_in[13];
    float* out = (float*)d_out;

    float *xn, *wqkv, *qkv, *attn, *x2, *y, *h1, *wor, *w1r, *w2r;
    cudaGetSymbolAddress((void**)&xn,   g_xn);
    cudaGetSymbolAddress((void**)&wqkv, g_wqkv);
    cudaGetSymbolAddress((void**)&qkv,  g_qkv);
    cudaGetSymbolAddress((void**)&attn, g_attn);
    cudaGetSymbolAddress((void**)&x2,   g_x2);
    cudaGetSymbolAddress((void**)&y,    g_y);
    cudaGetSymbolAddress((void**)&h1,   g_h1);
    cudaGetSymbolAddress((void**)&wor,  g_wor);
    cudaGetSymbolAddress((void**)&w1r,  g_w1r);
    cudaGetSymbolAddress((void**)&w2r,  g_w2r);

    const int SM_DENSE = (2 * 128 * 36 + 2 * 32 * 136) * 4;  // 71680

    cudaFuncSetAttribute(gemm_tc<128,128,32,0,0>, cudaFuncAttributeMaxDynamicSharedMemorySize, SM_DENSE);
    cudaFuncSetAttribute(gemm_tc<128,128,32,0,1>, cudaFuncAttributeMaxDynamicSharedMemorySize, SM_DENSE);
    cudaFuncSetAttribute(gemm_tc<128,128,32,1,1>, cudaFuncAttributeMaxDynamicSharedMemorySize, SM_DENSE);
    cudaFuncSetAttribute(flash_kernel, cudaFuncAttributeMaxDynamicSharedMemorySize, FSM_BYTES);

    // 0) pre-round weights to tf32
    round_kernel<<<(CC * CC + 255) / 256, 256>>>(Wo, wor, CC * CC);
    round_kernel<<<(CC * MLPD + 255) / 256, 256>>>(W1, w1r, CC * MLPD);
    round_kernel<<<(MLPD * CC + 255) / 256, 256>>>(W2, w2r, MLPD * CC);

    // 1) repack qkv weights (tf32)
    repack_kernel<<<(CC * QKVN + 255) / 256, 256>>>(Wq, Wk, Wv, wqkv);

    // 2) LN1 (tf32 out)
    ln_kernel<<<MR, 256>>>(x, ln1g, ln1b, xn);

    // 3) QKV GEMM: [8192,768] x [768,2304], tf32-rounded output
    gemm_tc<128,128,32,0,1><<<dim3(QKVN/128, MR/128, 1), 256, SM_DENSE>>>(
        MR, QKVN, CC, xn, CC, wqkv, QKVN, qkv, QKVN, nullptr, nullptr, 0);

    // 4-6) flash attention -> attn (head-concat, tf32 out)
    flash_kernel<<<dim3(TT/128, NBH), 256, FSM_BYTES>>>(qkv, attn);

    // 7) x2 = attn @ Wo + bo + x  (fp32 out)
    gemm_tc<128,128,32,0,0><<<dim3(CC/128, MR/128, 1), 256, SM_DENSE>>>(
        MR, CC, CC, attn, CC, wor, CC, x2, CC, bo, x, CC);

    // 8) LN2 (tf32 out)
    ln_kernel<<<MR, 256>>>(x2, ln2g, ln2b, y);

    // 9) h1 = gelu(y @ W1 + b1), tf32-rounded output
    gemm_tc<128,128,32,1,1><<<dim3(MLPD/128, MR/128, 1), 256, SM_DENSE>>>(
        MR, MLPD, CC, y, CC, w1r, MLPD, h1, MLPD, b1, nullptr, 0);

    // 10) out = x2 + (h1 @ W2 + b2)  (fp32 out)
    gemm_tc<128,128,32,0,0><<<dim3(CC/128, MR/128, 1), 256, SM_DENSE>>>(
        MR, CC, MLPD, h1, MLPD, w2r, CC, out, CC, b2, x2, CC);
}

// round 5
// speedup vs baseline: 3.9162x; 1.0017x over previous
#include <cuda_runtime.h>
#include <cstdint>
#include <math.h>

// ---------------------------------------------------------------------------
// Problem constants
// ---------------------------------------------------------------------------
#define BB   4
#define TT   2048
#define CC   768
#define HH   12
#define DD   64
#define MLPD 3072
#define MR   (BB*TT)        /* 8192 */
#define QKVN (3*CC)         /* 2304 */
#define NBH  (BB*HH)        /* 48 */

#define SCALE_F 0.03608439182435161f  /* 768^-0.5 */

// ---------------------------------------------------------------------------
// Scratch (device globals; no allocation allowed)
// ---------------------------------------------------------------------------
__device__ float g_xn  [MR * CC];
__device__ float g_wqkv[CC * QKVN];
__device__ float g_qkv [MR * QKVN];
__device__ float g_attn[MR * CC];
__device__ float g_x2  [MR * CC];
__device__ float g_y   [MR * CC];
__device__ float g_h1  [MR * MLPD];
__device__ float g_wor [CC * CC];
__device__ float g_w1r [CC * MLPD];
__device__ float g_w2r [MLPD * CC];

// ---------------------------------------------------------------------------
// Helpers
// ---------------------------------------------------------------------------
__device__ __forceinline__ void cp16(uint32_t dst, const void* src) {
    asm volatile("cp.async.cg.shared.global [%0], [%1], 16;\n" :: "r"(dst), "l"(src));
}
__device__ __forceinline__ uint32_t f2tf32(float v) {
    uint32_t u;
    asm("cvt.rna.tf32.f32 %0, %1;\n" : "=r"(u) : "f"(v));
    return u;
}
__device__ __forceinline__ float tf32r(float v) { return __uint_as_float(f2tf32(v)); }
__device__ __forceinline__ void mma_tf32(float& c0, float& c1, float& c2, float& c3,
                                         uint32_t a0, uint32_t a1, uint32_t a2, uint32_t a3,
                                         uint32_t b0, uint32_t b1) {
    asm volatile("mma.sync.aligned.m16n8k8.row.col.f32.tf32.tf32.f32 "
                 "{%0,%1,%2,%3}, {%4,%5,%6,%7}, {%8,%9}, {%0,%1,%2,%3};\n"
                 : "+f"(c0), "+f"(c1), "+f"(c2), "+f"(c3)
                 : "r"(a0), "r"(a1), "r"(a2), "r"(a3), "r"(b0), "r"(b1));
}
__device__ __forceinline__ float gelu_exact(float v) {
    return 0.5f * v * (1.0f + erff(v * 0.70710678118654752f));
}

// ---------------------------------------------------------------------------
// Pre-round an fp32 array to tf32 bit patterns
// ---------------------------------------------------------------------------
__global__ void round_kernel(const float* __restrict__ in, float* __restrict__ out, int n) {
    int i = blockIdx.x * 256 + threadIdx.x;
    if (i < n) out[i] = tf32r(in[i]);
}

// ---------------------------------------------------------------------------
// Repack Wq/Wk/Wv [H,C,D] -> row-major [C, 3C], tf32 pre-rounded
// ---------------------------------------------------------------------------
__global__ void repack_kernel(const float* __restrict__ Wq,
                              const float* __restrict__ Wk,
                              const float* __restrict__ Wv,
                              float* __restrict__ out) {
    int i = blockIdx.x * 256 + threadIdx.x;
    if (i >= CC * QKVN) return;
    int c  = i / QKVN;
    int n  = i % QKVN;
    int s  = n / CC;
    int hd = n % CC;
    int h  = hd / DD;
    int d  = hd % DD;
    const float* W = (s == 0) ? Wq : ((s == 1) ? Wk : Wv);
    out[i] = tf32r(W[((long long)h * CC + c) * DD + d]);
}

// ---------------------------------------------------------------------------
// LayerNorm: block per row, 256 threads, C=768; output tf32 pre-rounded
// ---------------------------------------------------------------------------
__global__ void ln_kernel(const float* __restrict__ x,
                          const float* __restrict__ g,
                          const float* __restrict__ b,
                          float* __restrict__ out) {
    int row = blockIdx.x;
    int tid = threadIdx.x;
    const float* xr = x + (long long)row * CC;
    float* orow = out + (long long)row * CC;

    float v0 = xr[tid], v1 = xr[tid + 256], v2 = xr[tid + 512];
    float s  = v0 + v1 + v2;
    float s2 = v0 * v0 + v1 * v1 + v2 * v2;

    __shared__ float sh1[256], sh2[256];
    sh1[tid] = s; sh2[tid] = s2;
    __syncthreads();
    #pragma unroll
    for (int o = 128; o > 0; o >>= 1) {
        if (tid < o) { sh1[tid] += sh1[tid + o]; sh2[tid] += sh2[tid + o]; }
        __syncthreads();
    }
    float mean = sh1[0] * (1.0f / CC);
    float var  = sh2[0] * (1.0f / CC) - mean * mean;
    float rstd = rsqrtf(var + 1e-6f);

    orow[tid]       = tf32r((v0 - mean) * rstd * g[tid]       + b[tid]);
    orow[tid + 256] = tf32r((v1 - mean) * rstd * g[tid + 256] + b[tid + 256]);
    orow[tid + 512] = tf32r((v2 - mean) * rstd * g[tid + 512] + b[tid + 512]);
}

// ---------------------------------------------------------------------------
// Tensor-core tf32 GEMM: C = act(A*B + bias) + res  (inputs pre-rounded tf32)
//   A: [M,K] row-major;  B: [K,N] row-major;  C: [M,N]
//   3-stage cp.async multistage pipeline, ONE __syncthreads per K-chunk.
//   8 warps: 2x4 grid of 64x32 warp tiles; m16n8k8 tf32 mma
// ---------------------------------------------------------------------------
#define GBM 128
#define GBN 128
#define GBK 32
#define GSTG 3
#define GASTR (GBK + 4)
#define GBSTR (GBN + 8)
#define GASTAGE (GBM * GASTR)
#define GBSTAGE (GBK * GBSTR)
#define SM_DENSE (GSTG * (GASTAGE + GBSTAGE) * 4)   /* 107520 */

template <int ACT, int TFOUT>
__global__ void __launch_bounds__(256)
gemm_tc(int M, int N, int K,
        const float* __restrict__ A, int lda,
        const float* __restrict__ B, int ldb,
        float* __restrict__ C, int ldc,
        const float* __restrict__ bias,
        const float* __restrict__ res, int ldres) {
    constexpr int MT = 4, NT = 4;   // 64x32 warp tile

    extern __shared__ float sm[];
    float* As = sm;
    float* Bs = sm + GSTG * GASTAGE;

    int tile_m = blockIdx.y * GBM, tile_n = blockIdx.x * GBN;
    int tid = threadIdx.x;
    int wid = tid >> 5, lane = tid & 31;
    int warp_m = wid >> 2, warp_n = wid & 3;
    int g = lane >> 2, t = lane & 3;

    uint32_t as_base = (uint32_t)__cvta_generic_to_shared(As);
    uint32_t bs_base = (uint32_t)__cvta_generic_to_shared(Bs);

    float acc[MT][NT][4];
    #pragma unroll
    for (int i = 0; i < MT; i++)
        #pragma unroll
        for (int j = 0; j < NT; j++)
            #pragma unroll
            for (int l = 0; l < 4; l++) acc[i][j][l] = 0.0f;

    auto load_stage = [&](int st, int k0) {
        #pragma unroll
        for (int idx = tid; idx < GBM * GBK / 4; idx += 256) {
            int r = idx / (GBK / 4);
            int c = (idx % (GBK / 4)) * 4;
            cp16(as_base + (uint32_t)((st * GBM + r) * GASTR + c) * 4,
                 A + (long long)(tile_m + r) * lda + k0 + c);
        }
        #pragma unroll
        for (int idx = tid; idx < GBK * GBN / 4; idx += 256) {
            int r = idx / (GBN / 4);
            int c = (idx % (GBN / 4)) * 4;
            cp16(bs_base + (uint32_t)((st * GBK + r) * GBSTR + c) * 4,
                 B + (long long)(k0 + r) * ldb + tile_n + c);
        }
        asm volatile("cp.async.commit_group;\n");
    };

    int nK = K / GBK;
    load_stage(0, 0);
    load_stage(1, GBK);

    int st = 0, ld_st = 2;
    for (int kt = 0; kt < nK; kt++) {
        if (kt + 1 < nK) { asm volatile("cp.async.wait_group 1;\n"); }
        else             { asm volatile("cp.async.wait_group 0;\n"); }
        __syncthreads();

        // prefetch stage kt+2 (writes stage (kt-1)%3, readers done by the sync)
        if (kt + 2 < nK) {
            load_stage(ld_st, (kt + 2) * GBK);
            if (++ld_st == GSTG) ld_st = 0;
        }

        const float* Ast = As + st * GASTAGE;
        const float* Bst = Bs + st * GBSTAGE;
        if (++st == GSTG) st = 0;

        #pragma unroll
        for (int ks = 0; ks < GBK / 8; ks++) {
            uint32_t af[MT][4];
            #pragma unroll
            for (int mt = 0; mt < MT; mt++) {
                int r = warp_m * 64 + mt * 16 + g;
                int c = ks * 8 + t;
                af[mt][0] = __float_as_uint(Ast[(r    ) * GASTR + c    ]);
                af[mt][1] = __float_as_uint(Ast[(r + 8) * GASTR + c    ]);
                af[mt][2] = __float_as_uint(Ast[(r    ) * GASTR + c + 4]);
                af[mt][3] = __float_as_uint(Ast[(r + 8) * GASTR + c + 4]);
            }
            uint32_t bf[NT][2];
            #pragma unroll
            for (int nt = 0; nt < NT; nt++) {
                int n = warp_n * 32 + nt * 8 + g;
                bf[nt][0] = __float_as_uint(Bst[(ks * 8 + t    ) * GBSTR + n]);
                bf[nt][1] = __float_as_uint(Bst[(ks * 8 + t + 4) * GBSTR + n]);
            }
            #pragma unroll
            for (int mt = 0; mt < MT; mt++)
                #pragma unroll
                for (int nt = 0; nt < NT; nt++)
                    mma_tf32(acc[mt][nt][0], acc[mt][nt][1], acc[mt][nt][2], acc[mt][nt][3],
                             af[mt][0], af[mt][1], af[mt][2], af[mt][3],
                             bf[nt][0], bf[nt][1]);
        }
        // no bottom barrier: next iteration's top barrier covers the hazard
    }

    #pragma unroll
    for (int mt = 0; mt < MT; mt++) {
        #pragma unroll
        for (int nt = 0; nt < NT; nt++) {
            int gm = tile_m + warp_m * 64 + mt * 16 + g;
            int gn = tile_n + warp_n * 32 + nt * 8 + t * 2;
            float v0 = acc[mt][nt][0];
            float v1 = acc[mt][nt][1];
            float v2 = acc[mt][nt][2];
            float v3 = acc[mt][nt][3];
            if (bias) {
                float2 bb = *(const float2*)&bias[gn];
                v0 += bb.x; v1 += bb.y; v2 += bb.x; v3 += bb.y;
            }
            if (ACT == 1) {
                v0 = gelu_exact(v0); v1 = gelu_exact(v1);
                v2 = gelu_exact(v2); v3 = gelu_exact(v3);
            }
            if (res) {
                float2 r0 = *(const float2*)&res[(long long)gm * ldres + gn];
                float2 r1 = *(const float2*)&res[(long long)(gm + 8) * ldres + gn];
                v0 += r0.x; v1 += r0.y; v2 += r1.x; v3 += r1.y;
            }
            if (TFOUT) {
                v0 = tf32r(v0); v1 = tf32r(v1); v2 = tf32r(v2); v3 = tf32r(v3);
            }
            *(float2*)&C[(long long)gm * ldc + gn]       = make_float2(v0, v1);
            *(float2*)&C[(long long)(gm + 8) * ldc + gn] = make_float2(v2, v3);
        }
    }
}

// ---------------------------------------------------------------------------
// Flash attention: one block = 128 Q rows of one (b,h).  (as R3)
// ---------------------------------------------------------------------------
#define QSTR 68
#define KSTR 68
#define VSTR 72
#define FSM_BYTES ((128*QSTR + 2*64*KSTR + 2*64*VSTR) * 4)

__global__ void __launch_bounds__(256)
flash_kernel(const float* __restrict__ qkv, float* __restrict__ attn) {
    extern __shared__ float sm[];
    float* QP = sm;
    float* Ks = sm + 128 * QSTR;
    float* Vs = Ks + 2 * 64 * KSTR;

    int z = blockIdx.y;
    int b = z / HH, h = z % HH;
    int t0 = blockIdx.x * 128;
    const float* Qg = qkv + (long long)b * TT * QKVN + h * DD;
    const float* Kg = Qg + CC;
    const float* Vg = Qg + 2 * CC;
    float* Og = attn + ((long long)b * TT + t0) * CC + h * DD;

    int tid = threadIdx.x, wid = tid >> 5, lane = tid & 31;
    int g = lane >> 2, t = lane & 3;

    uint32_t qp_base = (uint32_t)__cvta_generic_to_shared(QP);
    uint32_t k_base  = (uint32_t)__cvta_generic_to_shared(Ks);
    uint32_t v_base  = (uint32_t)__cvta_generic_to_shared(Vs);

    #pragma unroll
    for (int idx = tid; idx < 128 * 16; idx += 256) {
        int r = idx >> 4, c = (idx & 15) * 4;
        cp16(qp_base + (uint32_t)(r * QSTR + c) * 4,
             Qg + (long long)(t0 + r) * QKVN + c);
    }
    asm volatile("cp.async.commit_group;\n");

    auto loadKV = [&](int st, int key0) {
        #pragma unroll
        for (int idx = tid; idx < 64 * 16; idx += 256) {
            int r = idx >> 4, c = (idx & 15) * 4;
            cp16(k_base + (uint32_t)((st * 64 + r) * KSTR + c) * 4,
                 Kg + (long long)(key0 + r) * QKVN + c);
            cp16(v_base + (uint32_t)((st * 64 + r) * VSTR + c) * 4,
                 Vg + (long long)(key0 + r) * QKVN + c);
        }
    };
    loadKV(0, 0);
    asm volatile("cp.async.commit_group;\n");

    asm volatile("cp.async.wait_group 1;\n");
    __syncthreads();
    uint32_t qf[8][4];
    {
        int r0 = wid * 16 + g;
        #pragma unroll
        for (int ks = 0; ks < 8; ks++) {
            int c = ks * 8 + t;
            qf[ks][0] = f2tf32(QP[(r0    ) * QSTR + c    ] * SCALE_F);
            qf[ks][1] = f2tf32(QP[(r0 + 8) * QSTR + c    ] * SCALE_F);
            qf[ks][2] = f2tf32(QP[(r0    ) * QSTR + c + 4] * SCALE_F);
            qf[ks][3] = f2tf32(QP[(r0 + 8) * QSTR + c + 4] * SCALE_F);
        }
    }
    __syncthreads();

    float o[8][4];
    #pragma unroll
    for (int i = 0; i < 8; i++)
        #pragma unroll
        for (int l = 0; l < 4; l++) o[i][l] = 0.0f;
    float m0 = -1e30f, m1 = -1e30f, l0 = 0.0f, l1 = 0.0f;

    const int NCH = TT / 64;
    for (int j = 0; j < NCH; j++) {
        if (j + 1 < NCH) {
            loadKV((j + 1) & 1, (j + 1) * 64);
            asm volatile("cp.async.commit_group;\n");
            asm volatile("cp.async.wait_group 1;\n");
        } else {
            asm volatile("cp.async.wait_group 0;\n");
        }
        __syncthreads();

        const float* Kst = Ks + (j & 1) * 64 * KSTR;
        const float* Vst = Vs + (j & 1) * 64 * VSTR;

        float s[8][4];
        #pragma unroll
        for (int i = 0; i < 8; i++)
            #pragma unroll
            for (int l = 0; l < 4; l++) s[i][l] = 0.0f;

        #pragma unroll
        for (int ks = 0; ks < 8; ks++) {
            #pragma unroll
            for (int nt = 0; nt < 8; nt++) {
                uint32_t b0 = __float_as_uint(Kst[(nt * 8 + g) * KSTR + ks * 8 + t    ]);
                uint32_t b1 = __float_as_uint(Kst[(nt * 8 + g) * KSTR + ks * 8 + t + 4]);
                mma_tf32(s[nt][0], s[nt][1], s[nt][2], s[nt][3],
                         qf[ks][0], qf[ks][1], qf[ks][2], qf[ks][3], b0, b1);
            }
        }

        float cm0 = -1e30f, cm1 = -1e30f;
        #pragma unroll
        for (int nt = 0; nt < 8; nt++) {
            cm0 = fmaxf(cm0, fmaxf(s[nt][0], s[nt][1]));
            cm1 = fmaxf(cm1, fmaxf(s[nt][2], s[nt][3]));
        }
        cm0 = fmaxf(cm0, __shfl_xor_sync(0xffffffff, cm0, 1));
        cm0 = fmaxf(cm0, __shfl_xor_sync(0xffffffff, cm0, 2));
        cm1 = fmaxf(cm1, __shfl_xor_sync(0xffffffff, cm1, 1));
        cm1 = fmaxf(cm1, __shfl_xor_sync(0xffffffff, cm1, 2));

        float nm0 = fmaxf(m0, cm0), nm1 = fmaxf(m1, cm1);
        float a0 = __expf(m0 - nm0), a1 = __expf(m1 - nm1);
        l0 *= a0; l1 *= a1;
        #pragma unroll
        for (int nt = 0; nt < 8; nt++) {
            o[nt][0] *= a0; o[nt][1] *= a0; o[nt][2] *= a1; o[nt][3] *= a1;
        }

        int pr = wid * 16 + g;
        float rs0 = 0.0f, rs1 = 0.0f;
        #pragma unroll
        for (int nt = 0; nt < 8; nt++) {
            float p0 = __expf(s[nt][0] - nm0);
            float p1 = __expf(s[nt][1] - nm0);
            float p2 = __expf(s[nt][2] - nm1);
            float p3 = __expf(s[nt][3] - nm1);
            rs0 += p0 + p1; rs1 += p2 + p3;
            *(float2*)&QP[(pr    ) * QSTR + nt * 8 + 2 * t] =
                make_float2(tf32r(p0), tf32r(p1));
            *(float2*)&QP[(pr + 8) * QSTR + nt * 8 + 2 * t] =
                make_float2(tf32r(p2), tf32r(p3));
        }
        rs0 += __shfl_xor_sync(0xffffffff, rs0, 1);
        rs0 += __shfl_xor_sync(0xffffffff, rs0, 2);
        rs1 += __shfl_xor_sync(0xffffffff, rs1, 1);
        rs1 += __shfl_xor_sync(0xffffffff, rs1, 2);
        l0 += rs0; l1 += rs1;
        m0 = nm0; m1 = nm1;
        __syncwarp();

        #pragma unroll
        for (int ks = 0; ks < 8; ks++) {
            uint32_t af0 = __float_as_uint(QP[(pr    ) * QSTR + ks * 8 + t    ]);
            uint32_t af1 = __float_as_uint(QP[(pr + 8) * QSTR + ks * 8 + t    ]);
            uint32_t af2 = __float_as_uint(QP[(pr    ) * QSTR + ks * 8 + t + 4]);
            uint32_t af3 = __float_as_uint(QP[(pr + 8) * QSTR + ks * 8 + t + 4]);
            #pragma unroll
            for (int nt = 0; nt < 8; nt++) {
                uint32_t b0 = __float_as_uint(Vst[(ks * 8 + t    ) * VSTR + nt * 8 + g]);
                uint32_t b1 = __float_as_uint(Vst[(ks * 8 + t + 4) * VSTR + nt * 8 + g]);
                mma_tf32(o[nt][0], o[nt][1], o[nt][2], o[nt][3],
                         af0, af1, af2, af3, b0, b1);
            }
        }
        __syncthreads();
    }

    float r0 = 1.0f / l0, r1 = 1.0f / l1;
    int row = wid * 16 + g;
    #pragma unroll
    for (int nt = 0; nt < 8; nt++) {
        int cn = nt * 8 + 2 * t;
        *(float2*)&Og[(long long)(row    ) * CC + cn] =
            make_float2(tf32r(o[nt][0] * r0), tf32r(o[nt][1] * r0));
        *(float2*)&Og[(long long)(row + 8) * CC + cn] =
            make_float2(tf32r(o[nt][2] * r1), tf32r(o[nt][3] * r1));
    }
}

// ---------------------------------------------------------------------------
// kernel_launch
// ---------------------------------------------------------------------------
extern "C" void kernel_launch(void* const* d_in, const int* in_sizes, int n_in,
                              void* d_out, int out_size) {
    const float* x    = (const float*)d_in[0];
    const float* Wq   = (const float*)d_in[1];
    const float* Wk   = (const float*)d_in[2];
    const float* Wv   = (const float*)d_in[3];
    const float* Wo   = (const float*)d_in[4];
    const float* bo   = (const float*)d_in[5];
    const float* ln1g = (const float*)d_in[6];
    const float* ln1b = (const float*)d_in[7];
    const float* ln2g = (const float*)d_in[8];
    const float* ln2b = (const float*)d_in[9];
    const float* W1   = (const float*)d_in[10];
    const float* b1   = (const float*)d_in[11];
    const float* W2   = (const float*)d_in[12];
    const float* b2   = (const float*)d_in[13];
    float* out = (float*)d_out;

    float *xn, *wqkv, *qkv, *attn, *x2, *y, *h1, *wor, *w1r, *w2r;
    cudaGetSymbolAddress((void**)&xn,   g_xn);
    cudaGetSymbolAddress((void**)&wqkv, g_wqkv);
    cudaGetSymbolAddress((void**)&qkv,  g_qkv);
    cudaGetSymbolAddress((void**)&attn, g_attn);
    cudaGetSymbolAddress((void**)&x2,   g_x2);
    cudaGetSymbolAddress((void**)&y,    g_y);
    cudaGetSymbolAddress((void**)&h1,   g_h1);
    cudaGetSymbolAddress((void**)&wor,  g_wor);
    cudaGetSymbolAddress((void**)&w1r,  g_w1r);
    cudaGetSymbolAddress((void**)&w2r,  g_w2r);

    cudaFuncSetAttribute(gemm_tc<0,0>, cudaFuncAttributeMaxDynamicSharedMemorySize, SM_DENSE);
    cudaFuncSetAttribute(gemm_tc<0,1>, cudaFuncAttributeMaxDynamicSharedMemorySize, SM_DENSE);
    cudaFuncSetAttribute(gemm_tc<1,1>, cudaFuncAttributeMaxDynamicSharedMemorySize, SM_DENSE);
    cudaFuncSetAttribute(flash_kernel, cudaFuncAttributeMaxDynamicSharedMemorySize, FSM_BYTES);

    // 0) pre-round weights to tf32
    round_kernel<<<(CC * CC + 255) / 256, 256>>>(Wo, wor, CC * CC);
    round_kernel<<<(CC * MLPD + 255) / 256, 256>>>(W1, w1r, CC * MLPD);
    round_kernel<<<(MLPD * CC + 255) / 256, 256>>>(W2, w2r, MLPD * CC);

    // 1) repack qkv weights (tf32)
    repack_kernel<<<(CC * QKVN + 255) / 256, 256>>>(Wq, Wk, Wv, wqkv);

    // 2) LN1 (tf32 out)
    ln_kernel<<<MR, 256>>>(x, ln1g, ln1b, xn);

    // 3) QKV GEMM: [8192,768] x [768,2304], tf32-rounded output
    gemm_tc<0,1><<<dim3(QKVN/128, MR/128, 1), 256, SM_DENSE>>>(
        MR, QKVN, CC, xn, CC, wqkv, QKVN, qkv, QKVN, nullptr, nullptr, 0);

    // 4-6) flash attention -> attn (head-concat, tf32 out)
    flash_kernel<<<dim3(TT/128, NBH), 256, FSM_BYTES>>>(qkv, attn);

    // 7) x2 = attn @ Wo + bo + x  (fp32 out)
    gemm_tc<0,0><<<dim3(CC/128, MR/128, 1), 256, SM_DENSE>>>(
        MR, CC, CC, attn, CC, wor, CC, x2, CC, bo, x, CC);

    // 8) LN2 (tf32 out)
    ln_kernel<<<MR, 256>>>(x2, ln2g, ln2b, y);

    // 9) h1 = gelu(y @ W1 + b1), tf32-rounded output
    gemm_tc<1,1><<<dim3(MLPD/128, MR/128, 1), 256, SM_DENSE>>>(
        MR, MLPD, CC, y, CC, w1r, MLPD, h1, MLPD, b1, nullptr, 0);

    // 10) out = x2 + (h1 @ W2 + b2)  (fp32 out)
    gemm_tc<0,0><<<dim3(CC/128, MR/128, 1), 256, SM_DENSE>>>(
        MR, CC, MLPD, h1, MLPD, w2r, CC, out, CC, b2, x2, CC);
}

// round 6
// speedup vs baseline: 4.0550x; 1.0355x over previous
#include <cuda_runtime.h>
#include <cstdint>
#include <math.h>

// ---------------------------------------------------------------------------
// Problem constants
// ---------------------------------------------------------------------------
#define BB   4
#define TT   2048
#define CC   768
#define HH   12
#define DD   64
#define MLPD 3072
#define MR   (BB*TT)        /* 8192 */
#define QKVN (3*CC)         /* 2304 */
#define NBH  (BB*HH)        /* 48 */

#define SCALE_F 0.03608439182435161f  /* 768^-0.5 */

// ---------------------------------------------------------------------------
// Scratch (device globals; no allocation allowed)
// ---------------------------------------------------------------------------
__device__ float g_xn   [MR * CC];
__device__ float g_wqkvT[QKVN * CC];   // [N,K] tf32
__device__ float g_qkv  [MR * QKVN];
__device__ float g_attn [MR * CC];
__device__ float g_x2   [MR * CC];
__device__ float g_y    [MR * CC];
__device__ float g_h1   [MR * MLPD];
__device__ float g_woT  [CC * CC];     // [N,K] tf32
__device__ float g_w1T  [MLPD * CC];   // [N,K] tf32
__device__ float g_w2T  [CC * MLPD];   // [N,K] tf32

// ---------------------------------------------------------------------------
// Helpers
// ---------------------------------------------------------------------------
__device__ __forceinline__ void cp16(uint32_t dst, const void* src) {
    asm volatile("cp.async.cg.shared.global [%0], [%1], 16;\n" :: "r"(dst), "l"(src));
}
__device__ __forceinline__ uint32_t f2tf32(float v) {
    uint32_t u;
    asm("cvt.rna.tf32.f32 %0, %1;\n" : "=r"(u) : "f"(v));
    return u;
}
__device__ __forceinline__ float tf32r(float v) { return __uint_as_float(f2tf32(v)); }
__device__ __forceinline__ void mma_tf32(float& c0, float& c1, float& c2, float& c3,
                                         uint32_t a0, uint32_t a1, uint32_t a2, uint32_t a3,
                                         uint32_t b0, uint32_t b1) {
    asm volatile("mma.sync.aligned.m16n8k8.row.col.f32.tf32.tf32.f32 "
                 "{%0,%1,%2,%3}, {%4,%5,%6,%7}, {%8,%9}, {%0,%1,%2,%3};\n"
                 : "+f"(c0), "+f"(c1), "+f"(c2), "+f"(c3)
                 : "r"(a0), "r"(a1), "r"(a2), "r"(a3), "r"(b0), "r"(b1));
}
// ldmatrix x4 (b16 view; each 8x8-b16 submatrix == 8x4 tf32)
__device__ __forceinline__ void ldsm4(uint32_t& r0, uint32_t& r1, uint32_t& r2, uint32_t& r3,
                                      uint32_t addr) {
    asm volatile("ldmatrix.sync.aligned.m8n8.x4.shared.b16 {%0,%1,%2,%3}, [%4];\n"
                 : "=r"(r0), "=r"(r1), "=r"(r2), "=r"(r3) : "r"(addr));
}
__device__ __forceinline__ float gelu_exact(float v) {
    return 0.5f * v * (1.0f + erff(v * 0.70710678118654752f));
}

// ---------------------------------------------------------------------------
// Tiled transpose + tf32 round: out[Cn,R] = tf32(in[R,Cn]^T)
// ---------------------------------------------------------------------------
__global__ void transpose_round(const float* __restrict__ in, float* __restrict__ out,
                                int R, int Cn) {
    __shared__ float t[32][33];
    int bx = blockIdx.x * 32, by = blockIdx.y * 32;
    for (int dy = threadIdx.y; dy < 32; dy += 8)
        t[dy][threadIdx.x] = in[(size_t)(by + dy) * Cn + bx + threadIdx.x];
    __syncthreads();
    for (int dy = threadIdx.y; dy < 32; dy += 8)
        out[(size_t)(bx + dy) * R + by + threadIdx.x] = tf32r(t[threadIdx.x][dy]);
}

// ---------------------------------------------------------------------------
// Repack Wq/Wk/Wv [H,C,D] -> [3C rows(N), C cols(K)] tf32: out[s*768+h*64+d][c]
// ---------------------------------------------------------------------------
__global__ void repackT_kernel(const float* __restrict__ Wq,
                               const float* __restrict__ Wk,
                               const float* __restrict__ Wv,
                               float* __restrict__ out) {
    __shared__ float t[32][33];
    int z = blockIdx.z;
    int s = z / HH, h = z % HH;
    const float* W = (s == 0) ? Wq : ((s == 1) ? Wk : Wv);
    const float* Wh = W + (size_t)h * CC * DD;
    int c0 = blockIdx.x * 32, d0 = blockIdx.y * 32;
    for (int dy = threadIdx.y; dy < 32; dy += 8)
        t[dy][threadIdx.x] = Wh[(size_t)(c0 + dy) * DD + d0 + threadIdx.x];
    __syncthreads();
    int base = s * CC + h * DD;
    for (int dy = threadIdx.y; dy < 32; dy += 8)
        out[(size_t)(base + d0 + dy) * CC + c0 + threadIdx.x] = tf32r(t[threadIdx.x][dy]);
}

// ---------------------------------------------------------------------------
// LayerNorm: block per row, 256 threads, C=768; output tf32 pre-rounded
// ---------------------------------------------------------------------------
__global__ void ln_kernel(const float* __restrict__ x,
                          const float* __restrict__ g,
                          const float* __restrict__ b,
                          float* __restrict__ out) {
    int row = blockIdx.x;
    int tid = threadIdx.x;
    const float* xr = x + (long long)row * CC;
    float* orow = out + (long long)row * CC;

    float v0 = xr[tid], v1 = xr[tid + 256], v2 = xr[tid + 512];
    float s  = v0 + v1 + v2;
    float s2 = v0 * v0 + v1 * v1 + v2 * v2;

    __shared__ float sh1[256], sh2[256];
    sh1[tid] = s; sh2[tid] = s2;
    __syncthreads();
    #pragma unroll
    for (int o = 128; o > 0; o >>= 1) {
        if (tid < o) { sh1[tid] += sh1[tid + o]; sh2[tid] += sh2[tid + o]; }
        __syncthreads();
    }
    float mean = sh1[0] * (1.0f / CC);
    float var  = sh2[0] * (1.0f / CC) - mean * mean;
    float rstd = rsqrtf(var + 1e-6f);

    orow[tid]       = tf32r((v0 - mean) * rstd * g[tid]       + b[tid]);
    orow[tid + 256] = tf32r((v1 - mean) * rstd * g[tid + 256] + b[tid + 256]);
    orow[tid + 512] = tf32r((v2 - mean) * rstd * g[tid + 512] + b[tid + 512]);
}

// ---------------------------------------------------------------------------
// Tensor-core tf32 GEMM: C = act(A*Bt^T + bias) + res  (inputs pre-rounded tf32)
//   A: [M,K] row-major;  Bt: [N,K] row-major (K-major);  C: [M,N]
//   3-stage cp.async pipeline, one __syncthreads per K-chunk,
//   ldmatrix fragment loads for both operands.
// ---------------------------------------------------------------------------
#define GBM 128
#define GBN 128
#define GBK 32
#define GSTG 3
#define GSTR (GBK + 4)                    /* 36 floats per row */
#define GSTAGE (GBM * GSTR)               /* floats per operand stage */
#define SM_DENSE (GSTG * 2 * GSTAGE * 4)  /* 110592 bytes */

template <int ACT, int TFOUT>
__global__ void __launch_bounds__(256, 2)
gemm_tc(int M, int N, int K,
        const float* __restrict__ A, int lda,
        const float* __restrict__ Bt, int ldb,
        float* __restrict__ C, int ldc,
        const float* __restrict__ bias,
        const float* __restrict__ res, int ldres) {
    constexpr int MT = 4, NT = 4;   // 64x32 warp tile

    extern __shared__ float sm[];
    float* As = sm;
    float* Bs = sm + GSTG * GSTAGE;

    int tile_m = blockIdx.y * GBM, tile_n = blockIdx.x * GBN;
    int tid = threadIdx.x;
    int wid = tid >> 5, lane = tid & 31;
    int warp_m = wid >> 2, warp_n = wid & 3;
    int g = lane >> 2, t = lane & 3;

    uint32_t as_base = (uint32_t)__cvta_generic_to_shared(As);
    uint32_t bs_base = (uint32_t)__cvta_generic_to_shared(Bs);

    // ldmatrix lane address offsets (bytes)
    // A x4: m0 rows +0 cols +0 | m1 rows +8 cols +0 | m2 rows +0 cols +4 | m3 rows +8 cols +4
    int ra = (lane & 7) + ((lane >> 3) & 1) * 8;
    int ca = (lane >> 4) * 4;
    uint32_t a_off = (uint32_t)(((warp_m * 64 + ra) * GSTR + ca) * 4);
    // B x4: m0 rows +0 cols +0 | m1 rows +0 cols +4 | m2 rows +8 cols +0 | m3 rows +8 cols +4
    int rb = (lane & 7) + (lane >> 4) * 8;
    int cb = ((lane >> 3) & 1) * 4;
    uint32_t b_off = (uint32_t)(((warp_n * 32 + rb) * GSTR + cb) * 4);

    float acc[MT][NT][4];
    #pragma unroll
    for (int i = 0; i < MT; i++)
        #pragma unroll
        for (int j = 0; j < NT; j++)
            #pragma unroll
            for (int l = 0; l < 4; l++) acc[i][j][l] = 0.0f;

    auto load_stage = [&](int st, int k0) {
        #pragma unroll
        for (int idx = tid; idx < GBM * (GBK / 4); idx += 256) {
            int r = idx >> 3;
            int c = (idx & 7) * 4;
            cp16(as_base + (uint32_t)((st * GBM + r) * GSTR + c) * 4,
                 A + (long long)(tile_m + r) * lda + k0 + c);
        }
        #pragma unroll
        for (int idx = tid; idx < GBN * (GBK / 4); idx += 256) {
            int r = idx >> 3;
            int c = (idx & 7) * 4;
            cp16(bs_base + (uint32_t)((st * GBN + r) * GSTR + c) * 4,
                 Bt + (long long)(tile_n + r) * ldb + k0 + c);
        }
        asm volatile("cp.async.commit_group;\n");
    };

    int nK = K / GBK;
    load_stage(0, 0);
    load_stage(1, GBK);

    int st = 0, ld_st = 2;
    for (int kt = 0; kt < nK; kt++) {
        if (kt + 1 < nK) { asm volatile("cp.async.wait_group 1;\n"); }
        else             { asm volatile("cp.async.wait_group 0;\n"); }
        __syncthreads();

        if (kt + 2 < nK) {
            load_stage(ld_st, (kt + 2) * GBK);
            if (++ld_st == GSTG) ld_st = 0;
        }

        uint32_t aS = as_base + (uint32_t)(st * GSTAGE * 4) + a_off;
        uint32_t bS = bs_base + (uint32_t)(st * GSTAGE * 4) + b_off;
        if (++st == GSTG) st = 0;

        #pragma unroll
        for (int ks = 0; ks < GBK / 8; ks++) {
            uint32_t af[MT][4];
            #pragma unroll
            for (int mt = 0; mt < MT; mt++)
                ldsm4(af[mt][0], af[mt][1], af[mt][2], af[mt][3],
                      aS + (uint32_t)(mt * 16 * GSTR * 4 + ks * 32));
            uint32_t bf[2][4];
            #pragma unroll
            for (int np = 0; np < 2; np++)
                ldsm4(bf[np][0], bf[np][1], bf[np][2], bf[np][3],
                      bS + (uint32_t)(np * 16 * GSTR * 4 + ks * 32));
            #pragma unroll
            for (int mt = 0; mt < MT; mt++)
                #pragma unroll
                for (int nt = 0; nt < NT; nt++) {
                    const uint32_t* bp = &bf[nt >> 1][(nt & 1) * 2];
                    mma_tf32(acc[mt][nt][0], acc[mt][nt][1], acc[mt][nt][2], acc[mt][nt][3],
                             af[mt][0], af[mt][1], af[mt][2], af[mt][3],
                             bp[0], bp[1]);
                }
        }
    }

    #pragma unroll
    for (int mt = 0; mt < MT; mt++) {
        #pragma unroll
        for (int nt = 0; nt < NT; nt++) {
            int gm = tile_m + warp_m * 64 + mt * 16 + g;
            int gn = tile_n + warp_n * 32 + nt * 8 + t * 2;
            float v0 = acc[mt][nt][0];
            float v1 = acc[mt][nt][1];
            float v2 = acc[mt][nt][2];
            float v3 = acc[mt][nt][3];
            if (bias) {
                float2 bb = *(const float2*)&bias[gn];
                v0 += bb.x; v1 += bb.y; v2 += bb.x; v3 += bb.y;
            }
            if (ACT == 1) {
                v0 = gelu_exact(v0); v1 = gelu_exact(v1);
                v2 = gelu_exact(v2); v3 = gelu_exact(v3);
            }
            if (res) {
                float2 r0 = *(const float2*)&res[(long long)gm * ldres + gn];
                float2 r1 = *(const float2*)&res[(long long)(gm + 8) * ldres + gn];
                v0 += r0.x; v1 += r0.y; v2 += r1.x; v3 += r1.y;
            }
            if (TFOUT) {
                v0 = tf32r(v0); v1 = tf32r(v1); v2 = tf32r(v2); v3 = tf32r(v3);
            }
            *(float2*)&C[(long long)gm * ldc + gn]       = make_float2(v0, v1);
            *(float2*)&C[(long long)(gm + 8) * ldc + gn] = make_float2(v2, v3);
        }
    }
}

// ---------------------------------------------------------------------------
// Flash attention: one block = 128 Q rows of one (b,h).  (as R3/R5)
// ---------------------------------------------------------------------------
#define QSTR 68
#define KSTR 68
#define VSTR 72
#define FSM_BYTES ((128*QSTR + 2*64*KSTR + 2*64*VSTR) * 4)

__global__ void __launch_bounds__(256)
flash_kernel(const float* __restrict__ qkv, float* __restrict__ attn) {
    extern __shared__ float sm[];
    float* QP = sm;
    float* Ks = sm + 128 * QSTR;
    float* Vs = Ks + 2 * 64 * KSTR;

    int z = blockIdx.y;
    int b = z / HH, h = z % HH;
    int t0 = blockIdx.x * 128;
    const float* Qg = qkv + (long long)b * TT * QKVN + h * DD;
    const float* Kg = Qg + CC;
    const float* Vg = Qg + 2 * CC;
    float* Og = attn + ((long long)b * TT + t0) * CC + h * DD;

    int tid = threadIdx.x, wid = tid >> 5, lane = tid & 31;
    int g = lane >> 2, t = lane & 3;

    uint32_t qp_base = (uint32_t)__cvta_generic_to_shared(QP);
    uint32_t k_base  = (uint32_t)__cvta_generic_to_shared(Ks);
    uint32_t v_base  = (uint32_t)__cvta_generic_to_shared(Vs);

    #pragma unroll
    for (int idx = tid; idx < 128 * 16; idx += 256) {
        int r = idx >> 4, c = (idx & 15) * 4;
        cp16(qp_base + (uint32_t)(r * QSTR + c) * 4,
             Qg + (long long)(t0 + r) * QKVN + c);
    }
    asm volatile("cp.async.commit_group;\n");

    auto loadKV = [&](int st, int key0) {
        #pragma unroll
        for (int idx = tid; idx < 64 * 16; idx += 256) {
            int r = idx >> 4, c = (idx & 15) * 4;
            cp16(k_base + (uint32_t)((st * 64 + r) * KSTR + c) * 4,
                 Kg + (long long)(key0 + r) * QKVN + c);
            cp16(v_base + (uint32_t)((st * 64 + r) * VSTR + c) * 4,
                 Vg + (long long)(key0 + r) * QKVN + c);
        }
    };
    loadKV(0, 0);
    asm volatile("cp.async.commit_group;\n");

    asm volatile("cp.async.wait_group 1;\n");
    __syncthreads();
    uint32_t qf[8][4];
    {
        int r0 = wid * 16 + g;
        #pragma unroll
        for (int ks = 0; ks < 8; ks++) {
            int c = ks * 8 + t;
            qf[ks][0] = f2tf32(QP[(r0    ) * QSTR + c    ] * SCALE_F);
            qf[ks][1] = f2tf32(QP[(r0 + 8) * QSTR + c    ] * SCALE_F);
            qf[ks][2] = f2tf32(QP[(r0    ) * QSTR + c + 4] * SCALE_F);
            qf[ks][3] = f2tf32(QP[(r0 + 8) * QSTR + c + 4] * SCALE_F);
        }
    }
    __syncthreads();

    float o[8][4];
    #pragma unroll
    for (int i = 0; i < 8; i++)
        #pragma unroll
        for (int l = 0; l < 4; l++) o[i][l] = 0.0f;
    float m0 = -1e30f, m1 = -1e30f, l0 = 0.0f, l1 = 0.0f;

    const int NCH = TT / 64;
    for (int j = 0; j < NCH; j++) {
        if (j + 1 < NCH) {
            loadKV((j + 1) & 1, (j + 1) * 64);
            asm volatile("cp.async.commit_group;\n");
            asm volatile("cp.async.wait_group 1;\n");
        } else {
            asm volatile("cp.async.wait_group 0;\n");
        }
        __syncthreads();

        const float* Kst = Ks + (j & 1) * 64 * KSTR;
        const float* Vst = Vs + (j & 1) * 64 * VSTR;

        float s[8][4];
        #pragma unroll
        for (int i = 0; i < 8; i++)
            #pragma unroll
            for (int l = 0; l < 4; l++) s[i][l] = 0.0f;

        #pragma unroll
        for (int ks = 0; ks < 8; ks++) {
            #pragma unroll
            for (int nt = 0; nt < 8; nt++) {
                uint32_t b0 = __float_as_uint(Kst[(nt * 8 + g) * KSTR + ks * 8 + t    ]);
                uint32_t b1 = __float_as_uint(Kst[(nt * 8 + g) * KSTR + ks * 8 + t + 4]);
                mma_tf32(s[nt][0], s[nt][1], s[nt][2], s[nt][3],
                         qf[ks][0], qf[ks][1], qf[ks][2], qf[ks][3], b0, b1);
            }
        }

        float cm0 = -1e30f, cm1 = -1e30f;
        #pragma unroll
        for (int nt = 0; nt < 8; nt++) {
            cm0 = fmaxf(cm0, fmaxf(s[nt][0], s[nt][1]));
            cm1 = fmaxf(cm1, fmaxf(s[nt][2], s[nt][3]));
        }
        cm0 = fmaxf(cm0, __shfl_xor_sync(0xffffffff, cm0, 1));
        cm0 = fmaxf(cm0, __shfl_xor_sync(0xffffffff, cm0, 2));
        cm1 = fmaxf(cm1, __shfl_xor_sync(0xffffffff, cm1, 1));
        cm1 = fmaxf(cm1, __shfl_xor_sync(0xffffffff, cm1, 2));

        float nm0 = fmaxf(m0, cm0), nm1 = fmaxf(m1, cm1);
        float a0 = __expf(m0 - nm0), a1 = __expf(m1 - nm1);
        l0 *= a0; l1 *= a1;
        #pragma unroll
        for (int nt = 0; nt < 8; nt++) {
            o[nt][0] *= a0; o[nt][1] *= a0; o[nt][2] *= a1; o[nt][3] *= a1;
        }

        int pr = wid * 16 + g;
        float rs0 = 0.0f, rs1 = 0.0f;
        #pragma unroll
        for (int nt = 0; nt < 8; nt++) {
            float p0 = __expf(s[nt][0] - nm0);
            float p1 = __expf(s[nt][1] - nm0);
            float p2 = __expf(s[nt][2] - nm1);
            float p3 = __expf(s[nt][3] - nm1);
            rs0 += p0 + p1; rs1 += p2 + p3;
            *(float2*)&QP[(pr    ) * QSTR + nt * 8 + 2 * t] =
                make_float2(tf32r(p0), tf32r(p1));
            *(float2*)&QP[(pr + 8) * QSTR + nt * 8 + 2 * t] =
                make_float2(tf32r(p2), tf32r(p3));
        }
        rs0 += __shfl_xor_sync(0xffffffff, rs0, 1);
        rs0 += __shfl_xor_sync(0xffffffff, rs0, 2);
        rs1 += __shfl_xor_sync(0xffffffff, rs1, 1);
        rs1 += __shfl_xor_sync(0xffffffff, rs1, 2);
        l0 += rs0; l1 += rs1;
        m0 = nm0; m1 = nm1;
        __syncwarp();

        #pragma unroll
        for (int ks = 0; ks < 8; ks++) {
            uint32_t af0 = __float_as_uint(QP[(pr    ) * QSTR + ks * 8 + t    ]);
            uint32_t af1 = __float_as_uint(QP[(pr + 8) * QSTR + ks * 8 + t    ]);
            uint32_t af2 = __float_as_uint(QP[(pr    ) * QSTR + ks * 8 + t + 4]);
            uint32_t af3 = __float_as_uint(QP[(pr + 8) * QSTR + ks * 8 + t + 4]);
            #pragma unroll
            for (int nt = 0; nt < 8; nt++) {
                uint32_t b0 = __float_as_uint(Vst[(ks * 8 + t    ) * VSTR + nt * 8 + g]);
                uint32_t b1 = __float_as_uint(Vst[(ks * 8 + t + 4) * VSTR + nt * 8 + g]);
                mma_tf32(o[nt][0], o[nt][1], o[nt][2], o[nt][3],
                         af0, af1, af2, af3, b0, b1);
            }
        }
        __syncthreads();
    }

    float r0 = 1.0f / l0, r1 = 1.0f / l1;
    int row = wid * 16 + g;
    #pragma unroll
    for (int nt = 0; nt < 8; nt++) {
        int cn = nt * 8 + 2 * t;
        *(float2*)&Og[(long long)(row    ) * CC + cn] =
            make_float2(tf32r(o[nt][0] * r0), tf32r(o[nt][1] * r0));
        *(float2*)&Og[(long long)(row + 8) * CC + cn] =
            make_float2(tf32r(o[nt][2] * r1), tf32r(o[nt][3] * r1));
    }
}

// ---------------------------------------------------------------------------
// kernel_launch
// ---------------------------------------------------------------------------
extern "C" void kernel_launch(void* const* d_in, const int* in_sizes, int n_in,
                              void* d_out, int out_size) {
    const float* x    = (const float*)d_in[0];
    const float* Wq   = (const float*)d_in[1];
    const float* Wk   = (const float*)d_in[2];
    const float* Wv   = (const float*)d_in[3];
    const float* Wo   = (const float*)d_in[4];
    const float* bo   = (const float*)d_in[5];
    const float* ln1g = (const float*)d_in[6];
    const float* ln1b = (const float*)d_in[7];
    const float* ln2g = (const float*)d_in[8];
    const float* ln2b = (const float*)d_in[9];
    const float* W1   = (const float*)d_in[10];
    const float* b1   = (const float*)d_in[11];
    const float* W2   = (const float*)d_in[12];
    const float* b2   = (const float*)d_in[13];
    float* out = (float*)d_out;

    float *xn, *wqkvT, *qkv, *attn, *x2, *y, *h1, *woT, *w1T, *w2T;
    cudaGetSymbolAddress((void**)&xn,    g_xn);
    cudaGetSymbolAddress((void**)&wqkvT, g_wqkvT);
    cudaGetSymbolAddress((void**)&qkv,   g_qkv);
    cudaGetSymbolAddress((void**)&attn,  g_attn);
    cudaGetSymbolAddress((void**)&x2,    g_x2);
    cudaGetSymbolAddress((void**)&y,     g_y);
    cudaGetSymbolAddress((void**)&h1,    g_h1);
    cudaGetSymbolAddress((void**)&woT,   g_woT);
    cudaGetSymbolAddress((void**)&w1T,   g_w1T);
    cudaGetSymbolAddress((void**)&w2T,   g_w2T);

    cudaFuncSetAttribute(gemm_tc<0,0>, cudaFuncAttributeMaxDynamicSharedMemorySize, SM_DENSE);
    cudaFuncSetAttribute(gemm_tc<0,1>, cudaFuncAttributeMaxDynamicSharedMemorySize, SM_DENSE);
    cudaFuncSetAttribute(gemm_tc<1,1>, cudaFuncAttributeMaxDynamicSharedMemorySize, SM_DENSE);
    cudaFuncSetAttribute(flash_kernel, cudaFuncAttributeMaxDynamicSharedMemorySize, FSM_BYTES);

    dim3 tb(32, 8);

    // 0) weights: transpose + tf32-round  ([N,K] layouts)
    repackT_kernel<<<dim3(CC/32, DD/32, 36), tb>>>(Wq, Wk, Wv, wqkvT);
    transpose_round<<<dim3(CC/32,   CC/32),   tb>>>(Wo, woT, CC, CC);
    transpose_round<<<dim3(MLPD/32, CC/32),   tb>>>(W1, w1T, CC, MLPD);
    transpose_round<<<dim3(CC/32,   MLPD/32), tb>>>(W2, w2T, MLPD, CC);

    // 1) LN1 (tf32 out)
    ln_kernel<<<MR, 256>>>(x, ln1g, ln1b, xn);

    // 2) QKV GEMM: [8192,768] x [2304,768]^T, tf32-rounded output
    gemm_tc<0,1><<<dim3(QKVN/128, MR/128), 256, SM_DENSE>>>(
        MR, QKVN, CC, xn, CC, wqkvT, CC, qkv, QKVN, nullptr, nullptr, 0);

    // 3) flash attention -> attn (head-concat, tf32 out)
    flash_kernel<<<dim3(TT/128, NBH), 256, FSM_BYTES>>>(qkv, attn);

    // 4) x2 = attn @ Wo + bo + x  (fp32 out)
    gemm_tc<0,0><<<dim3(CC/128, MR/128), 256, SM_DENSE>>>(
        MR, CC, CC, attn, CC, woT, CC, x2, CC, bo, x, CC);

    // 5) LN2 (tf32 out)
    ln_kernel<<<MR, 256>>>(x2, ln2g, ln2b, y);

    // 6) h1 = gelu(y @ W1 + b1), tf32 out
    gemm_tc<1,1><<<dim3(MLPD/128, MR/128), 256, SM_DENSE>>>(
        MR, MLPD, CC, y, CC, w1T, CC, h1, MLPD, b1, nullptr, 0);

    // 7) out = x2 + (h1 @ W2 + b2)  (fp32 out)
    gemm_tc<0,0><<<dim3(CC/128, MR/128), 256, SM_DENSE>>>(
        MR, CC, MLPD, h1, MLPD, w2T, MLPD, out, CC, b2, x2, CC);
}

// round 7
// speedup vs baseline: 7.2361x; 1.7845x over previous
#include <cuda_runtime.h>
#include <cuda_fp16.h>
#include <cstdint>
#include <math.h>

// ---------------------------------------------------------------------------
// Problem constants
// ---------------------------------------------------------------------------
#define BB   4
#define TT   2048
#define CC   768
#define HH   12
#define DD   64
#define MLPD 3072
#define MR   (BB*TT)        /* 8192 */
#define QKVN (3*CC)         /* 2304 */
#define NBH  (BB*HH)        /* 48 */

#define SCALE_F 0.03608439182435161f  /* 768^-0.5 */

// ---------------------------------------------------------------------------
// Scratch (device globals; no allocation allowed)
// ---------------------------------------------------------------------------
__device__ __half g_xn   [MR * CC];
__device__ __half g_wqkvT[QKVN * CC];   // [N,K]
__device__ __half g_qkv  [MR * QKVN];   // q section pre-scaled by SCALE_F
__device__ __half g_attn [MR * CC];
__device__ float  g_x2   [MR * CC];
__device__ __half g_y    [MR * CC];
__device__ __half g_h1   [MR * MLPD];
__device__ __half g_woT  [CC * CC];     // [N,K]
__device__ __half g_w1T  [MLPD * CC];   // [N,K]
__device__ __half g_w2T  [CC * MLPD];   // [N,K]

// ---------------------------------------------------------------------------
// Helpers
// ---------------------------------------------------------------------------
__device__ __forceinline__ void cp16(uint32_t dst, const void* src) {
    asm volatile("cp.async.cg.shared.global [%0], [%1], 16;\n" :: "r"(dst), "l"(src));
}
__device__ __forceinline__ uint32_t h2(float a, float b) {
    __half2 v = __floats2half2_rn(a, b);
    return *(uint32_t*)&v;
}
__device__ __forceinline__ void mma_f16(float& c0, float& c1, float& c2, float& c3,
                                        uint32_t a0, uint32_t a1, uint32_t a2, uint32_t a3,
                                        uint32_t b0, uint32_t b1) {
    asm volatile("mma.sync.aligned.m16n8k16.row.col.f32.f16.f16.f32 "
                 "{%0,%1,%2,%3}, {%4,%5,%6,%7}, {%8,%9}, {%0,%1,%2,%3};\n"
                 : "+f"(c0), "+f"(c1), "+f"(c2), "+f"(c3)
                 : "r"(a0), "r"(a1), "r"(a2), "r"(a3), "r"(b0), "r"(b1));
}
__device__ __forceinline__ void ldsm4(uint32_t& r0, uint32_t& r1, uint32_t& r2, uint32_t& r3,
                                      uint32_t addr) {
    asm volatile("ldmatrix.sync.aligned.m8n8.x4.shared.b16 {%0,%1,%2,%3}, [%4];\n"
                 : "=r"(r0), "=r"(r1), "=r"(r2), "=r"(r3) : "r"(addr));
}
__device__ __forceinline__ void ldsm4t(uint32_t& r0, uint32_t& r1, uint32_t& r2, uint32_t& r3,
                                       uint32_t addr) {
    asm volatile("ldmatrix.sync.aligned.m8n8.x4.trans.shared.b16 {%0,%1,%2,%3}, [%4];\n"
                 : "=r"(r0), "=r"(r1), "=r"(r2), "=r"(r3) : "r"(addr));
}
__device__ __forceinline__ float gelu_exact(float v) {
    return 0.5f * v * (1.0f + erff(v * 0.70710678118654752f));
}

// ---------------------------------------------------------------------------
// Tiled transpose + fp16 round: out[Cn,R] = half(in[R,Cn]^T)
// ---------------------------------------------------------------------------
__global__ void transpose_round(const float* __restrict__ in, __half* __restrict__ out,
                                int R, int Cn) {
    __shared__ float t[32][33];
    int bx = blockIdx.x * 32, by = blockIdx.y * 32;
    for (int dy = threadIdx.y; dy < 32; dy += 8)
        t[dy][threadIdx.x] = in[(size_t)(by + dy) * Cn + bx + threadIdx.x];
    __syncthreads();
    for (int dy = threadIdx.y; dy < 32; dy += 8)
        out[(size_t)(bx + dy) * R + by + threadIdx.x] = __float2half_rn(t[threadIdx.x][dy]);
}

// ---------------------------------------------------------------------------
// Repack Wq/Wk/Wv [H,C,D] -> [3C(N), C(K)] fp16: out[s*768+h*64+d][c]
// ---------------------------------------------------------------------------
__global__ void repackT_kernel(const float* __restrict__ Wq,
                               const float* __restrict__ Wk,
                               const float* __restrict__ Wv,
                               __half* __restrict__ out) {
    __shared__ float t[32][33];
    int z = blockIdx.z;
    int s = z / HH, h = z % HH;
    const float* W = (s == 0) ? Wq : ((s == 1) ? Wk : Wv);
    const float* Wh = W + (size_t)h * CC * DD;
    int c0 = blockIdx.x * 32, d0 = blockIdx.y * 32;
    for (int dy = threadIdx.y; dy < 32; dy += 8)
        t[dy][threadIdx.x] = Wh[(size_t)(c0 + dy) * DD + d0 + threadIdx.x];
    __syncthreads();
    int base = s * CC + h * DD;
    for (int dy = threadIdx.y; dy < 32; dy += 8)
        out[(size_t)(base + d0 + dy) * CC + c0 + threadIdx.x] =
            __float2half_rn(t[threadIdx.x][dy]);
}

// ---------------------------------------------------------------------------
// LayerNorm: block per row, 256 threads, C=768; fp16 output
// ---------------------------------------------------------------------------
__global__ void ln_kernel(const float* __restrict__ x,
                          const float* __restrict__ g,
                          const float* __restrict__ b,
                          __half* __restrict__ out) {
    int row = blockIdx.x;
    int tid = threadIdx.x;
    const float* xr = x + (long long)row * CC;
    __half* orow = out + (long long)row * CC;

    float v0 = xr[tid], v1 = xr[tid + 256], v2 = xr[tid + 512];
    float s  = v0 + v1 + v2;
    float s2 = v0 * v0 + v1 * v1 + v2 * v2;

    __shared__ float sh1[256], sh2[256];
    sh1[tid] = s; sh2[tid] = s2;
    __syncthreads();
    #pragma unroll
    for (int o = 128; o > 0; o >>= 1) {
        if (tid < o) { sh1[tid] += sh1[tid + o]; sh2[tid] += sh2[tid + o]; }
        __syncthreads();
    }
    float mean = sh1[0] * (1.0f / CC);
    float var  = sh2[0] * (1.0f / CC) - mean * mean;
    float rstd = rsqrtf(var + 1e-6f);

    orow[tid]       = __float2half_rn((v0 - mean) * rstd * g[tid]       + b[tid]);
    orow[tid + 256] = __float2half_rn((v1 - mean) * rstd * g[tid + 256] + b[tid + 256]);
    orow[tid + 512] = __float2half_rn((v2 - mean) * rstd * g[tid + 512] + b[tid + 512]);
}

// ---------------------------------------------------------------------------
// fp16 tensor-core GEMM: C = act(A*Bt^T + bias) + res
//   A: [M,K] half row-major;  Bt: [N,K] half row-major;  C: float or half
//   BK=64 halves, 3-stage cp.async, ldmatrix, m16n8k16 fp32-accum mma.
//   QS: multiply cols < 768 by SCALE_F (q pre-scaling for flash)
// ---------------------------------------------------------------------------
#define GBM 128
#define GBN 128
#define GBK 64
#define GSTG 3
#define GSTR (GBK + 8)                     /* 72 halves per row (144 B) */
#define GSTAGE (GBM * GSTR)                /* halves per operand stage */
#define SM_DENSE (GSTG * 2 * GSTAGE * 2)   /* 110592 bytes */

template <int ACT, int OUTH, int QS>
__global__ void __launch_bounds__(256, 2)
gemm_tc(int M, int N, int K,
        const __half* __restrict__ A, int lda,
        const __half* __restrict__ Bt, int ldb,
        float* __restrict__ Cf, __half* __restrict__ Ch, int ldc,
        const float* __restrict__ bias,
        const float* __restrict__ res, int ldres) {
    constexpr int MT = 4, NT = 4;   // 64x32 warp tile

    extern __shared__ __half smh[];
    uint32_t as_base = (uint32_t)__cvta_generic_to_shared(smh);
    uint32_t bs_base = as_base + GSTG * GSTAGE * 2;

    int tile_m = blockIdx.y * GBM, tile_n = blockIdx.x * GBN;
    int tid = threadIdx.x;
    int wid = tid >> 5, lane = tid & 31;
    int warp_m = wid >> 2, warp_n = wid & 3;
    int g = lane >> 2, t = lane & 3;

    // ldmatrix lane offsets (bytes)
    // A x4: m0 rows0-7/k0-7, m1 rows8-15/k0-7, m2 rows0-7/k8-15, m3 rows8-15/k8-15
    uint32_t a_off = (uint32_t)((warp_m * 64 + (lane & 15)) * GSTR * 2 + (lane >> 4) * 16);
    // B x4: m0 n0-7/k0-7, m1 n0-7/k8-15, m2 n8-15/k0-7, m3 n8-15/k8-15
    uint32_t b_off = (uint32_t)((warp_n * 32 + (lane & 7) + (lane >> 4) * 8) * GSTR * 2
                                + ((lane >> 3) & 1) * 16);

    float acc[MT][NT][4];
    #pragma unroll
    for (int i = 0; i < MT; i++)
        #pragma unroll
        for (int j = 0; j < NT; j++)
            #pragma unroll
            for (int l = 0; l < 4; l++) acc[i][j][l] = 0.0f;

    auto load_stage = [&](int st, int k0) {
        #pragma unroll
        for (int idx = tid; idx < GBM * 8; idx += 256) {
            int r = idx >> 3;
            int c = idx & 7;
            cp16(as_base + (uint32_t)((st * GBM + r) * GSTR * 2 + c * 16),
                 A + (long long)(tile_m + r) * lda + k0 + c * 8);
        }
        #pragma unroll
        for (int idx = tid; idx < GBN * 8; idx += 256) {
            int r = idx >> 3;
            int c = idx & 7;
            cp16(bs_base + (uint32_t)((st * GBN + r) * GSTR * 2 + c * 16),
                 Bt + (long long)(tile_n + r) * ldb + k0 + c * 8);
        }
        asm volatile("cp.async.commit_group;\n");
    };

    int nK = K / GBK;
    load_stage(0, 0);
    load_stage(1, GBK);

    int st = 0, ld_st = 2;
    for (int kt = 0; kt < nK; kt++) {
        if (kt + 1 < nK) { asm volatile("cp.async.wait_group 1;\n"); }
        else             { asm volatile("cp.async.wait_group 0;\n"); }
        __syncthreads();

        if (kt + 2 < nK) {
            load_stage(ld_st, (kt + 2) * GBK);
            if (++ld_st == GSTG) ld_st = 0;
        }

        uint32_t aS = as_base + (uint32_t)(st * GSTAGE * 2) + a_off;
        uint32_t bS = bs_base + (uint32_t)(st * GSTAGE * 2) + b_off;
        if (++st == GSTG) st = 0;

        #pragma unroll
        for (int ks = 0; ks < GBK / 16; ks++) {   // 4 k16-steps
            uint32_t af[MT][4];
            #pragma unroll
            for (int mt = 0; mt < MT; mt++)
                ldsm4(af[mt][0], af[mt][1], af[mt][2], af[mt][3],
                      aS + (uint32_t)(mt * 16 * GSTR * 2 + ks * 32));
            uint32_t bf[2][4];
            #pragma unroll
            for (int np = 0; np < 2; np++)
                ldsm4(bf[np][0], bf[np][1], bf[np][2], bf[np][3],
                      bS + (uint32_t)(np * 16 * GSTR * 2 + ks * 32));
            #pragma unroll
            for (int mt = 0; mt < MT; mt++)
                #pragma unroll
                for (int nt = 0; nt < NT; nt++) {
                    const uint32_t* bp = &bf[nt >> 1][(nt & 1) * 2];
                    mma_f16(acc[mt][nt][0], acc[mt][nt][1], acc[mt][nt][2], acc[mt][nt][3],
                            af[mt][0], af[mt][1], af[mt][2], af[mt][3],
                            bp[0], bp[1]);
                }
        }
    }

    #pragma unroll
    for (int mt = 0; mt < MT; mt++) {
        #pragma unroll
        for (int nt = 0; nt < NT; nt++) {
            int gm = tile_m + warp_m * 64 + mt * 16 + g;
            int gn = tile_n + warp_n * 32 + nt * 8 + t * 2;
            float v0 = acc[mt][nt][0];
            float v1 = acc[mt][nt][1];
            float v2 = acc[mt][nt][2];
            float v3 = acc[mt][nt][3];
            if (bias) {
                float2 bb = *(const float2*)&bias[gn];
                v0 += bb.x; v1 += bb.y; v2 += bb.x; v3 += bb.y;
            }
            if (ACT == 1) {
                v0 = gelu_exact(v0); v1 = gelu_exact(v1);
                v2 = gelu_exact(v2); v3 = gelu_exact(v3);
            }
            if (res) {
                float2 r0 = *(const float2*)&res[(long long)gm * ldres + gn];
                float2 r1 = *(const float2*)&res[(long long)(gm + 8) * ldres + gn];
                v0 += r0.x; v1 += r0.y; v2 += r1.x; v3 += r1.y;
            }
            if (QS && gn < CC) {
                v0 *= SCALE_F; v1 *= SCALE_F; v2 *= SCALE_F; v3 *= SCALE_F;
            }
            if (OUTH) {
                *(__half2*)&Ch[(long long)gm * ldc + gn]       = __floats2half2_rn(v0, v1);
                *(__half2*)&Ch[(long long)(gm + 8) * ldc + gn] = __floats2half2_rn(v2, v3);
            } else {
                *(float2*)&Cf[(long long)gm * ldc + gn]       = make_float2(v0, v1);
                *(float2*)&Cf[(long long)(gm + 8) * ldc + gn] = make_float2(v2, v3);
            }
        }
    }
}

// ---------------------------------------------------------------------------
// fp16 flash attention: block = 128 Q rows of one (b,h); 8 warps x 16 rows.
// Q pre-scaled; K/V double-buffered 64-key chunks; S->P stays in registers.
// ---------------------------------------------------------------------------
#define QSTR 72
#define KSTR 72
#define VSTR 72
#define FSM_BYTES ((128*QSTR + 2*64*KSTR + 2*64*VSTR) * 2)   /* 55296 */

__global__ void __launch_bounds__(256)
flash_kernel(const __half* __restrict__ qkv, __half* __restrict__ attn) {
    extern __shared__ __half smh[];
    uint32_t q_base = (uint32_t)__cvta_generic_to_shared(smh);
    uint32_t k_base = q_base + 128 * QSTR * 2;
    uint32_t v_base = k_base + 2 * 64 * KSTR * 2;

    int z = blockIdx.y;
    int b = z / HH, h = z % HH;
    int t0 = blockIdx.x * 128;
    const __half* Qg = qkv + (long long)b * TT * QKVN + h * DD;
    const __half* Kg = Qg + CC;
    const __half* Vg = Qg + 2 * CC;
    __half* Og = attn + ((long long)b * TT + t0) * CC + h * DD;

    int tid = threadIdx.x, wid = tid >> 5, lane = tid & 31;
    int g = lane >> 2, t = lane & 3;

    // ---- load Q tile (own group) ----
    #pragma unroll
    for (int idx = tid; idx < 128 * 8; idx += 256) {
        int r = idx >> 3, c = idx & 7;
        cp16(q_base + (uint32_t)(r * QSTR * 2 + c * 16),
             Qg + (long long)(t0 + r) * QKVN + c * 8);
    }
    asm volatile("cp.async.commit_group;\n");

    auto loadKV = [&](int st, int key0) {
        #pragma unroll
        for (int idx = tid; idx < 64 * 8; idx += 256) {
            int r = idx >> 3, c = idx & 7;
            cp16(k_base + (uint32_t)((st * 64 + r) * KSTR * 2 + c * 16),
                 Kg + (long long)(key0 + r) * QKVN + c * 8);
            cp16(v_base + (uint32_t)((st * 64 + r) * VSTR * 2 + c * 16),
                 Vg + (long long)(key0 + r) * QKVN + c * 8);
        }
        asm volatile("cp.async.commit_group;\n");
    };
    loadKV(0, 0);

    // ---- Q fragments (Q pre-scaled in QKV epilogue) ----
    asm volatile("cp.async.wait_group 1;\n");   // Q done
    __syncthreads();
    uint32_t q_off = q_base + (uint32_t)((wid * 16 + (lane & 15)) * QSTR * 2
                                         + (lane >> 4) * 16);
    uint32_t qf[4][4];
    #pragma unroll
    for (int ks = 0; ks < 4; ks++)
        ldsm4(qf[ks][0], qf[ks][1], qf[ks][2], qf[ks][3], q_off + ks * 32);

    // ldmatrix lane offsets for K (non-trans) and V (trans)
    uint32_t k_off = (uint32_t)(((lane & 7) + (lane >> 4) * 8) * KSTR * 2
                                + ((lane >> 3) & 1) * 16);
    uint32_t v_off = (uint32_t)(((lane & 7) + ((lane >> 3) & 1) * 8) * VSTR * 2
                                + (lane >> 4) * 16);

    float o[8][4];
    #pragma unroll
    for (int i = 0; i < 8; i++)
        #pragma unroll
        for (int l = 0; l < 4; l++) o[i][l] = 0.0f;
    float m0 = -1e30f, m1 = -1e30f, l0 = 0.0f, l1 = 0.0f;

    const int NCH = TT / 64;  // 32
    for (int j = 0; j < NCH; j++) {
        asm volatile("cp.async.wait_group 0;\n");   // chunk j ready
        __syncthreads();                            // all warps past prev compute
        if (j + 1 < NCH) loadKV((j + 1) & 1, (j + 1) * 64);

        uint32_t Kst = k_base + (uint32_t)((j & 1) * 64 * KSTR * 2);
        uint32_t Vst = v_base + (uint32_t)((j & 1) * 64 * VSTR * 2);

        // ---- S = Q K^T : 16x64 per warp ----
        float s[8][4];
        #pragma unroll
        for (int i = 0; i < 8; i++)
            #pragma unroll
            for (int l = 0; l < 4; l++) s[i][l] = 0.0f;

        #pragma unroll
        for (int ks = 0; ks < 4; ks++) {           // d 16-steps
            #pragma unroll
            for (int nb = 0; nb < 4; nb++) {       // 16-key blocks
                uint32_t kf[4];
                ldsm4(kf[0], kf[1], kf[2], kf[3],
                      Kst + (uint32_t)(nb * 16 * KSTR * 2 + ks * 32) + k_off);
                mma_f16(s[nb*2][0], s[nb*2][1], s[nb*2][2], s[nb*2][3],
                        qf[ks][0], qf[ks][1], qf[ks][2], qf[ks][3], kf[0], kf[1]);
                mma_f16(s[nb*2+1][0], s[nb*2+1][1], s[nb*2+1][2], s[nb*2+1][3],
                        qf[ks][0], qf[ks][1], qf[ks][2], qf[ks][3], kf[2], kf[3]);
            }
        }

        // ---- online softmax (rows g / g+8) ----
        float cm0 = -1e30f, cm1 = -1e30f;
        #pragma unroll
        for (int nb = 0; nb < 8; nb++) {
            cm0 = fmaxf(cm0, fmaxf(s[nb][0], s[nb][1]));
            cm1 = fmaxf(cm1, fmaxf(s[nb][2], s[nb][3]));
        }
        cm0 = fmaxf(cm0, __shfl_xor_sync(0xffffffff, cm0, 1));
        cm0 = fmaxf(cm0, __shfl_xor_sync(0xffffffff, cm0, 2));
        cm1 = fmaxf(cm1, __shfl_xor_sync(0xffffffff, cm1, 1));
        cm1 = fmaxf(cm1, __shfl_xor_sync(0xffffffff, cm1, 2));

        float nm0 = fmaxf(m0, cm0), nm1 = fmaxf(m1, cm1);
        float a0 = __expf(m0 - nm0), a1 = __expf(m1 - nm1);
        l0 *= a0; l1 *= a1;
        #pragma unroll
        for (int nb = 0; nb < 8; nb++) {
            o[nb][0] *= a0; o[nb][1] *= a0; o[nb][2] *= a1; o[nb][3] *= a1;
        }

        float rs0 = 0.0f, rs1 = 0.0f;
        #pragma unroll
        for (int nb = 0; nb < 8; nb++) {
            s[nb][0] = __expf(s[nb][0] - nm0);
            s[nb][1] = __expf(s[nb][1] - nm0);
            s[nb][2] = __expf(s[nb][2] - nm1);
            s[nb][3] = __expf(s[nb][3] - nm1);
            rs0 += s[nb][0] + s[nb][1];
            rs1 += s[nb][2] + s[nb][3];
        }
        rs0 += __shfl_xor_sync(0xffffffff, rs0, 1);
        rs0 += __shfl_xor_sync(0xffffffff, rs0, 2);
        rs1 += __shfl_xor_sync(0xffffffff, rs1, 1);
        rs1 += __shfl_xor_sync(0xffffffff, rs1, 2);
        l0 += rs0; l1 += rs1;
        m0 = nm0; m1 = nm1;

        // ---- O += P V (P built in registers; V via ldmatrix.trans) ----
        #pragma unroll
        for (int jk = 0; jk < 4; jk++) {           // 16-key steps
            uint32_t pf0 = h2(s[2*jk  ][0], s[2*jk  ][1]);
            uint32_t pf1 = h2(s[2*jk  ][2], s[2*jk  ][3]);
            uint32_t pf2 = h2(s[2*jk+1][0], s[2*jk+1][1]);
            uint32_t pf3 = h2(s[2*jk+1][2], s[2*jk+1][3]);
            #pragma unroll
            for (int np = 0; np < 4; np++) {       // 16-d blocks
                uint32_t vf[4];
                ldsm4t(vf[0], vf[1], vf[2], vf[3],
                       Vst + (uint32_t)(jk * 16 * VSTR * 2 + np * 32) + v_off);
                mma_f16(o[np*2][0], o[np*2][1], o[np*2][2], o[np*2][3],
                        pf0, pf1, pf2, pf3, vf[0], vf[1]);
                mma_f16(o[np*2+1][0], o[np*2+1][1], o[np*2+1][2], o[np*2+1][3],
                        pf0, pf1, pf2, pf3, vf[2], vf[3]);
            }
        }
    }

    // ---- epilogue ----
    float r0 = 1.0f / l0, r1 = 1.0f / l1;
    int row = wid * 16 + g;
    #pragma unroll
    for (int nb = 0; nb < 8; nb++) {
        int cn = nb * 8 + 2 * t;
        *(__half2*)&Og[(long long)(row    ) * CC + cn] =
            __floats2half2_rn(o[nb][0] * r0, o[nb][1] * r0);
        *(__half2*)&Og[(long long)(row + 8) * CC + cn] =
            __floats2half2_rn(o[nb][2] * r1, o[nb][3] * r1);
    }
}

// ---------------------------------------------------------------------------
// kernel_launch
// ---------------------------------------------------------------------------
extern "C" void kernel_launch(void* const* d_in, const int* in_sizes, int n_in,
                              void* d_out, int out_size) {
    const float* x    = (const float*)d_in[0];
    const float* Wq   = (const float*)d_in[1];
    const float* Wk   = (const float*)d_in[2];
    const float* Wv   = (const float*)d_in[3];
    const float* Wo   = (const float*)d_in[4];
    const float* bo   = (const float*)d_in[5];
    const float* ln1g = (const float*)d_in[6];
    const float* ln1b = (const float*)d_in[7];
    const float* ln2g = (const float*)d_in[8];
    const float* ln2b = (const float*)d_in[9];
    const float* W1   = (const float*)d_in[10];
    const float* b1   = (const float*)d_in[11];
    const float* W2   = (const float*)d_in[12];
    const float* b2   = (const float*)d_in[13];
    float* out = (float*)d_out;

    __half *xn, *wqkvT, *qkv, *attn, *y, *h1, *woT, *w1T, *w2T;
    float *x2;
    cudaGetSymbolAddress((void**)&xn,    g_xn);
    cudaGetSymbolAddress((void**)&wqkvT, g_wqkvT);
    cudaGetSymbolAddress((void**)&qkv,   g_qkv);
    cudaGetSymbolAddress((void**)&attn,  g_attn);
    cudaGetSymbolAddress((void**)&x2,    g_x2);
    cudaGetSymbolAddress((void**)&y,     g_y);
    cudaGetSymbolAddress((void**)&h1,    g_h1);
    cudaGetSymbolAddress((void**)&woT,   g_woT);
    cudaGetSymbolAddress((void**)&w1T,   g_w1T);
    cudaGetSymbolAddress((void**)&w2T,   g_w2T);

    cudaFuncSetAttribute(gemm_tc<0,1,1>, cudaFuncAttributeMaxDynamicSharedMemorySize, SM_DENSE);
    cudaFuncSetAttribute(gemm_tc<0,0,0>, cudaFuncAttributeMaxDynamicSharedMemorySize, SM_DENSE);
    cudaFuncSetAttribute(gemm_tc<1,1,0>, cudaFuncAttributeMaxDynamicSharedMemorySize, SM_DENSE);
    cudaFuncSetAttribute(flash_kernel, cudaFuncAttributeMaxDynamicSharedMemorySize, FSM_BYTES);

    dim3 tb(32, 8);

    // 0) weights: transpose + fp16 round  ([N,K] layouts)
    repackT_kernel<<<dim3(CC/32, DD/32, 36), tb>>>(Wq, Wk, Wv, wqkvT);
    transpose_round<<<dim3(CC/32,   CC/32),   tb>>>(Wo, woT, CC, CC);
    transpose_round<<<dim3(MLPD/32, CC/32),   tb>>>(W1, w1T, CC, MLPD);
    transpose_round<<<dim3(CC/32,   MLPD/32), tb>>>(W2, w2T, MLPD, CC);

    // 1) LN1 (fp16 out)
    ln_kernel<<<MR, 256>>>(x, ln1g, ln1b, xn);

    // 2) QKV GEMM (q cols pre-scaled by SCALE_F), half out
    gemm_tc<0,1,1><<<dim3(QKVN/128, MR/128), 256, SM_DENSE>>>(
        MR, QKVN, CC, xn, CC, wqkvT, CC, nullptr, qkv, QKVN, nullptr, nullptr, 0);

    // 3) flash attention -> attn (head-concat, half)
    flash_kernel<<<dim3(TT/128, NBH), 256, FSM_BYTES>>>(qkv, attn);

    // 4) x2 = attn @ Wo + bo + x  (float out)
    gemm_tc<0,0,0><<<dim3(CC/128, MR/128), 256, SM_DENSE>>>(
        MR, CC, CC, attn, CC, woT, CC, x2, nullptr, CC, bo, x, CC);

    // 5) LN2 (fp16 out)
    ln_kernel<<<MR, 256>>>(x2, ln2g, ln2b, y);

    // 6) h1 = gelu(y @ W1 + b1), half out
    gemm_tc<1,1,0><<<dim3(MLPD/128, MR/128), 256, SM_DENSE>>>(
        MR, MLPD, CC, y, CC, w1T, CC, nullptr, h1, MLPD, b1, nullptr, 0);

    // 7) out = x2 + (h1 @ W2 + b2)  (float out)
    gemm_tc<0,0,0><<<dim3(CC/128, MR/128), 256, SM_DENSE>>>(
        MR, CC, MLPD, h1, MLPD, w2T, MLPD, out, nullptr, CC, b2, x2, CC);
}